// round 6
// baseline (speedup 1.0000x reference)
#include <cuda_runtime.h>
#include <cuda_bf16.h>
#include <math.h>
#include <stdint.h>

// ---------------------------------------------------------------------------
// Problem constants
// ---------------------------------------------------------------------------
constexpr int SEQ    = 2048;
constexpr int DIM    = 2048;
constexpr int NH     = 16;
constexpr int QR     = 1536;
constexpr int KVR    = 512;
constexpr int ROPE_D = 64;
constexpr int NOPE   = 128;
constexpr int VDIM   = 128;
constexpr int QKD    = NOPE + ROPE_D;          // 192
constexpr int KVUP_D = NOPE + VDIM;            // 256
constexpr float EPSF = 1e-6f;

// ---------------------------------------------------------------------------
// Scratch (device globals: allocation-free)
// ---------------------------------------------------------------------------
__device__ __align__(256) float g_cq   [SEQ * QR];
__device__ __align__(256) float g_q    [SEQ * NH * QKD];
__device__ __align__(256) float g_kv   [SEQ * (KVR + ROPE_D)];
__device__ __align__(256) float g_ckv  [SEQ * KVR];
__device__ __align__(256) float g_krope[SEQ * ROPE_D];
__device__ __align__(256) float g_kvup [SEQ * NH * KVUP_D];
__device__ __align__(256) float g_attn [SEQ * NH * VDIM];
__device__ __align__(256) float g_cos  [SEQ * (ROPE_D / 2)];
__device__ __align__(256) float g_sin  [SEQ * (ROPE_D / 2)];
// tf32-pre-rounded operand copies
__device__ __align__(256) float g_x    [SEQ * DIM];
__device__ __align__(256) float g_wqkvd[(QR + KVR + ROPE_D) * DIM];  // q_down | kv_down
__device__ __align__(256) float g_wqu  [NH * QKD * QR];
__device__ __align__(256) float g_wkvu [NH * KVUP_D * KVR];
__device__ __align__(256) float g_wo   [DIM * NH * VDIM];

// ---------------------------------------------------------------------------
// tf32 helpers
// ---------------------------------------------------------------------------
__device__ __forceinline__ uint32_t f2tf32(float f) {
    uint32_t u;
    asm("cvt.rna.tf32.f32 %0, %1;" : "=r"(u) : "f"(f));
    return u;
}
__device__ __forceinline__ float round_tf32(float f) {
    return __uint_as_float(f2tf32(f));
}

#define MMA_TF32(D0,D1,D2,D3,A0,A1,A2,A3,B0,B1)                              \
    asm volatile(                                                            \
        "mma.sync.aligned.m16n8k8.row.col.f32.tf32.tf32.f32 "                \
        "{%0,%1,%2,%3},{%4,%5,%6,%7},{%8,%9},{%0,%1,%2,%3};"                 \
        : "+f"(D0), "+f"(D1), "+f"(D2), "+f"(D3)                             \
        : "r"(A0), "r"(A1), "r"(A2), "r"(A3), "r"(B0), "r"(B1))

// ---------------------------------------------------------------------------
// Elementwise tf32 pre-rounding
// ---------------------------------------------------------------------------
__global__ void __launch_bounds__(256) round_tf32_kernel(
    const float4* __restrict__ src, float4* __restrict__ dst, int n4)
{
    for (int i = blockIdx.x * 256 + threadIdx.x; i < n4; i += gridDim.x * 256) {
        float4 v = src[i];
        v.x = round_tf32(v.x); v.y = round_tf32(v.y);
        v.z = round_tf32(v.z); v.w = round_tf32(v.w);
        dst[i] = v;
    }
}

// ---------------------------------------------------------------------------
// Tensor-core NT GEMM: C[M,N] = A[M,K] * B[N,K]^T, tf32-pre-rounded operands.
// 128x64x32 tiles, 8 warps each 64x16. 3-stage cp.async pipeline +
// double-buffered register fragments. 2 CTAs/SM.
// SPLIT: columns [0,N1) -> C (width N1), [N1,N) -> C2 (width N2).
// ---------------------------------------------------------------------------
constexpr int GBM = 128, GBN = 64, GBK = 32, GST = 36;
constexpr int GTILE_F = (GBM + GBN) * GST;            // floats per stage
constexpr int GSTAGES = 3;
constexpr int GEMM_SMEM = GSTAGES * GTILE_F * 4;      // 82944 B

template<bool SPLIT>
__global__ void __launch_bounds__(256, 2) gemm_tf32_kernel(
    const float* __restrict__ A, const float* __restrict__ B,
    float* __restrict__ C, float* __restrict__ C2,
    int M, int N, int N1, int N2, int K)
{
    extern __shared__ float smg[];

    const int tid  = threadIdx.x;
    const int warp = tid >> 5;
    const int lane = tid & 31;
    const int g    = lane >> 2;
    const int tg   = lane & 3;
    const int wm   = (warp & 1) * 64;
    const int wn   = (warp >> 1) * 16;
    const int bm0  = blockIdx.y * GBM;
    const int bn0  = blockIdx.x * GBN;

    const uint32_t s0 = (uint32_t)__cvta_generic_to_shared(smg);

    auto load_tiles = [&](int slot, int k0) {
        const uint32_t sA = s0 + slot * (GTILE_F * 4);
        const uint32_t sB = sA + GBM * GST * 4;
#pragma unroll
        for (int i = 0; i < 4; i++) {          // A: 1024 16B chunks
            const int c   = tid + i * 256;
            const int row = c >> 3;
            const int seg = c & 7;
            const uint32_t da = sA + (row * GST + seg * 4) * 4;
            const float* ga = A + (size_t)(bm0 + row) * K + k0 + seg * 4;
            asm volatile("cp.async.cg.shared.global [%0], [%1], 16;"
                         :: "r"(da), "l"(ga));
        }
#pragma unroll
        for (int i = 0; i < 2; i++) {          // B: 512 chunks
            const int c   = tid + i * 256;
            const int row = c >> 3;
            const int seg = c & 7;
            const int rb  = bn0 + row;
            const int ok  = (rb < N) ? 16 : 0;
            const float* gb = B + (size_t)(ok ? rb : 0) * K + k0 + seg * 4;
            const uint32_t db = sB + (row * GST + seg * 4) * 4;
            asm volatile("cp.async.cg.shared.global [%0], [%1], 16, %2;"
                         :: "r"(db), "l"(gb), "r"(ok));
        }
    };

    float acc[4][2][4];
#pragma unroll
    for (int mt = 0; mt < 4; mt++)
#pragma unroll
        for (int nt = 0; nt < 2; nt++)
#pragma unroll
            for (int v = 0; v < 4; v++) acc[mt][nt][v] = 0.f;

    const int nk = K / GBK;

    // prologue: STAGES-1 tiles in flight
#pragma unroll
    for (int s = 0; s < GSTAGES - 1; s++) {
        if (s < nk) load_tiles(s, s * GBK);
        asm volatile("cp.async.commit_group;");
    }

    uint32_t af[2][4][4], bf[2][2][2];

    auto load_frags = [&](int b, const float* sa, const float* sb, int k8) {
#pragma unroll
        for (int mt = 0; mt < 4; mt++) {
            const int r = wm + mt * 16 + g;
            af[b][mt][0] = __float_as_uint(sa[r       * GST + k8 + tg]);
            af[b][mt][1] = __float_as_uint(sa[(r + 8) * GST + k8 + tg]);
            af[b][mt][2] = __float_as_uint(sa[r       * GST + k8 + tg + 4]);
            af[b][mt][3] = __float_as_uint(sa[(r + 8) * GST + k8 + tg + 4]);
        }
#pragma unroll
        for (int nt = 0; nt < 2; nt++) {
            const int rn = wn + nt * 8 + g;
            bf[b][nt][0] = __float_as_uint(sb[rn * GST + k8 + tg]);
            bf[b][nt][1] = __float_as_uint(sb[rn * GST + k8 + tg + 4]);
        }
    };

    for (int kt = 0; kt < nk; kt++) {
        asm volatile("cp.async.wait_group %0;" :: "n"(GSTAGES - 2));
        __syncthreads();

        // prefetch tile kt+STAGES-1 into the buffer freed at tile kt-1
        if (kt + GSTAGES - 1 < nk)
            load_tiles((kt + GSTAGES - 1) % GSTAGES, (kt + GSTAGES - 1) * GBK);
        asm volatile("cp.async.commit_group;");

        const float* sa = smg + (kt % GSTAGES) * GTILE_F;
        const float* sb = sa + GBM * GST;

        load_frags(0, sa, sb, 0);
#pragma unroll
        for (int s8 = 0; s8 < GBK / 8; s8++) {
            if (s8 + 1 < GBK / 8)
                load_frags((s8 + 1) & 1, sa, sb, (s8 + 1) * 8);
            const int b = s8 & 1;
#pragma unroll
            for (int mt = 0; mt < 4; mt++)
#pragma unroll
                for (int nt = 0; nt < 2; nt++)
                    MMA_TF32(acc[mt][nt][0], acc[mt][nt][1],
                             acc[mt][nt][2], acc[mt][nt][3],
                             af[b][mt][0], af[b][mt][1],
                             af[b][mt][2], af[b][mt][3],
                             bf[b][nt][0], bf[b][nt][1]);
        }
    }

    // epilogue — pick destination (split boundary is tile-aligned)
    float* Cb; int Nw, c0;
    if (SPLIT && bn0 >= N1) { Cb = C2; Nw = N2; c0 = bn0 - N1; }
    else                    { Cb = C;  Nw = SPLIT ? N1 : N; c0 = bn0; }

#pragma unroll
    for (int mt = 0; mt < 4; mt++) {
        const int r0 = bm0 + wm + mt * 16 + g;
#pragma unroll
        for (int nt = 0; nt < 2; nt++) {
            const int cc = c0 + wn + nt * 8 + tg * 2;
            if (cc < Nw) {
                *reinterpret_cast<float2*>(&Cb[(size_t)r0 * Nw + cc]) =
                    make_float2(acc[mt][nt][0], acc[mt][nt][1]);
                *reinterpret_cast<float2*>(&Cb[(size_t)(r0 + 8) * Nw + cc]) =
                    make_float2(acc[mt][nt][2], acc[mt][nt][3]);
            }
        }
    }
}

// ---------------------------------------------------------------------------
// RMSNorm — output tf32-rounded
// ---------------------------------------------------------------------------
__global__ void __launch_bounds__(256) rmsnorm_kernel(
    const float* __restrict__ src, float* __restrict__ dst,
    const float* __restrict__ w, int R, int sstride, int dstride)
{
    const int row = blockIdx.x;
    const float* s = src + (size_t)row * sstride;
    float* d = dst + (size_t)row * dstride;

    float sum = 0.f;
    for (int i = threadIdx.x; i < R; i += 256) {
        float v = s[i];
        sum = fmaf(v, v, sum);
    }
    __shared__ float red[8];
#pragma unroll
    for (int o = 16; o; o >>= 1) sum += __shfl_down_sync(0xffffffffu, sum, o);
    if ((threadIdx.x & 31) == 0) red[threadIdx.x >> 5] = sum;
    __syncthreads();
    if (threadIdx.x < 8) {
        float v = red[threadIdx.x];
#pragma unroll
        for (int o = 4; o; o >>= 1) v += __shfl_down_sync(0xffu, v, o);
        if (threadIdx.x == 0) red[0] = v;
    }
    __syncthreads();
    const float mean = red[0] / (float)R;
    const float r = rsqrtf(mean + EPSF);
    for (int i = threadIdx.x; i < R; i += 256)
        d[i] = round_tf32(s[i] * r * w[i]);
}

// ---------------------------------------------------------------------------
// RoPE
// ---------------------------------------------------------------------------
__global__ void rope_tables_kernel()
{
    const int idx = blockIdx.x * blockDim.x + threadIdx.x;
    if (idx >= SEQ * (ROPE_D / 2)) return;
    const int t = idx / (ROPE_D / 2);
    const int i = idx % (ROPE_D / 2);
    const double freq = pow(500000.0, -(double)i / 32.0);
    const float ang = (float)t * (float)freq;
    g_cos[idx] = cosf(ang);
    g_sin[idx] = sinf(ang);
}

__global__ void rope_q_kernel()
{
    const int idx = blockIdx.x * blockDim.x + threadIdx.x;
    if (idx >= SEQ * NH * (ROPE_D / 2)) return;
    const int i  = idx & 31;
    const int th = idx >> 5;
    const int h  = th % NH;
    const int t  = th / NH;
    const float c = g_cos[t * 32 + i];
    const float s = g_sin[t * 32 + i];
    float* p = g_q + (size_t)t * (NH * QKD) + h * QKD + NOPE + 2 * i;
    const float e = p[0], o = p[1];
    p[0] = e * c - o * s;
    p[1] = o * c + e * s;
}

__global__ void rope_k_kernel()
{
    const int idx = blockIdx.x * blockDim.x + threadIdx.x;
    if (idx >= SEQ * (ROPE_D / 2)) return;
    const int i = idx & 31;
    const int t = idx >> 5;
    const float c = g_cos[t * 32 + i];
    const float s = g_sin[t * 32 + i];
    const float* src = g_kv + (size_t)t * (KVR + ROPE_D) + KVR + 2 * i;
    const float e = src[0], o = src[1];
    g_krope[t * ROPE_D + 2 * i]     = e * c - o * s;
    g_krope[t * ROPE_D + 2 * i + 1] = o * c + e * s;
}

// ---------------------------------------------------------------------------
// Tensor-core causal flash attention (unchanged from R5)
// ---------------------------------------------------------------------------
constexpr int QSTR = 200, VSTR = 72;
constexpr int ATT_SMEM_BYTES = (128 * QSTR + 64 * QSTR + 128 * VSTR) * 4;

__device__ __forceinline__ int kperm(int j) {
    return (j & 3) * 2 + (j >> 2);
}

__global__ void __launch_bounds__(256) attn_mma_kernel()
{
    extern __shared__ float sm[];
    float* Qs = sm;                     // [128][200]
    float* Ks = Qs + 128 * QSTR;        // [64][200]
    float* Vt = Ks + 64 * QSTR;         // [128][72]

    const int tid  = threadIdx.x;
    const int warp = tid >> 5;
    const int lane = tid & 31;
    const int g    = lane >> 2;
    const int tg   = lane & 3;
    const int bx   = blockIdx.x;
    const int qt   = (bx & 1) ? (15 - (bx >> 1)) : (bx >> 1);
    const int h    = blockIdx.y;
    const int qbase = qt * 128;
    const int r0   = warp * 16;
    const float scale = 0.07216878364870322f;  // 1/sqrt(192)

    for (int idx = tid; idx < 128 * 192; idx += 256) {
        const int r = idx / 192, d = idx % 192;
        const int pos = (d & ~7) + kperm(d & 7);
        Qs[r * QSTR + pos] =
            g_q[(size_t)(qbase + r) * (NH * QKD) + h * QKD + d] * scale;
    }

    float sacc[8][4];
    float oacc[16][4];
#pragma unroll
    for (int nv = 0; nv < 16; nv++)
#pragma unroll
        for (int v = 0; v < 4; v++) oacc[nv][v] = 0.f;
    float m0 = -INFINITY, m1 = -INFINITY, l0 = 0.f, l1 = 0.f;

    const int nkt = 2 * qt + 2;
    for (int kt = 0; kt < nkt; kt++) {
        const int kbase = kt * 64;
        __syncthreads();

        for (int idx = tid; idx < 64 * 192; idx += 256) {
            const int r = idx / 192, d = idx % 192;
            const int pos = (d & ~7) + kperm(d & 7);
            const float v = (d < NOPE)
                ? g_kvup[(size_t)(kbase + r) * (NH * KVUP_D) + h * KVUP_D + d]
                : g_krope[(size_t)(kbase + r) * ROPE_D + (d - NOPE)];
            Ks[r * QSTR + pos] = v;
        }
        for (int idx = tid; idx < 64 * 128; idx += 256) {
            const int r = idx >> 7, dv = idx & 127;
            const int pos = (r & ~7) + kperm(r & 7);
            Vt[dv * VSTR + pos] =
                g_kvup[(size_t)(kbase + r) * (NH * KVUP_D) + h * KVUP_D + NOPE + dv];
        }
        __syncthreads();

#pragma unroll
        for (int nf = 0; nf < 8; nf++)
#pragma unroll
            for (int v = 0; v < 4; v++) sacc[nf][v] = 0.f;

#pragma unroll
        for (int f = 0; f < 24; f++) {
            const float2 qa = *reinterpret_cast<const float2*>(
                &Qs[(r0 + g) * QSTR + f * 8 + tg * 2]);
            const float2 qb = *reinterpret_cast<const float2*>(
                &Qs[(r0 + g + 8) * QSTR + f * 8 + tg * 2]);
            const uint32_t a0 = f2tf32(qa.x), a1 = f2tf32(qb.x);
            const uint32_t a2 = f2tf32(qa.y), a3 = f2tf32(qb.y);
#pragma unroll
            for (int nf = 0; nf < 8; nf++) {
                const float2 kb = *reinterpret_cast<const float2*>(
                    &Ks[(nf * 8 + g) * QSTR + f * 8 + tg * 2]);
                MMA_TF32(sacc[nf][0], sacc[nf][1], sacc[nf][2], sacc[nf][3],
                         a0, a1, a2, a3, f2tf32(kb.x), f2tf32(kb.y));
            }
        }

        const int rg  = qbase + r0 + g;
        if (kbase + 63 > rg) {
#pragma unroll
            for (int nf = 0; nf < 8; nf++) {
                const int c0 = kbase + nf * 8 + tg * 2;
                if (c0     > rg)     sacc[nf][0] = -INFINITY;
                if (c0 + 1 > rg)     sacc[nf][1] = -INFINITY;
                if (c0     > rg + 8) sacc[nf][2] = -INFINITY;
                if (c0 + 1 > rg + 8) sacc[nf][3] = -INFINITY;
            }
        }

        float t0 = -INFINITY, t1 = -INFINITY;
#pragma unroll
        for (int nf = 0; nf < 8; nf++) {
            t0 = fmaxf(t0, fmaxf(sacc[nf][0], sacc[nf][1]));
            t1 = fmaxf(t1, fmaxf(sacc[nf][2], sacc[nf][3]));
        }
        t0 = fmaxf(t0, __shfl_xor_sync(0xffffffffu, t0, 1));
        t0 = fmaxf(t0, __shfl_xor_sync(0xffffffffu, t0, 2));
        t1 = fmaxf(t1, __shfl_xor_sync(0xffffffffu, t1, 1));
        t1 = fmaxf(t1, __shfl_xor_sync(0xffffffffu, t1, 2));
        const float nm0 = fmaxf(m0, t0), nm1 = fmaxf(m1, t1);
        const float al0 = __expf(m0 - nm0), al1 = __expf(m1 - nm1);
        m0 = nm0; m1 = nm1;

        float rs0 = 0.f, rs1 = 0.f;
#pragma unroll
        for (int nf = 0; nf < 8; nf++) {
            sacc[nf][0] = __expf(sacc[nf][0] - nm0);
            sacc[nf][1] = __expf(sacc[nf][1] - nm0);
            sacc[nf][2] = __expf(sacc[nf][2] - nm1);
            sacc[nf][3] = __expf(sacc[nf][3] - nm1);
            rs0 += sacc[nf][0] + sacc[nf][1];
            rs1 += sacc[nf][2] + sacc[nf][3];
        }
        rs0 += __shfl_xor_sync(0xffffffffu, rs0, 1);
        rs0 += __shfl_xor_sync(0xffffffffu, rs0, 2);
        rs1 += __shfl_xor_sync(0xffffffffu, rs1, 1);
        rs1 += __shfl_xor_sync(0xffffffffu, rs1, 2);
        l0 = l0 * al0 + rs0;
        l1 = l1 * al1 + rs1;

#pragma unroll
        for (int nv = 0; nv < 16; nv++) {
            oacc[nv][0] *= al0; oacc[nv][1] *= al0;
            oacc[nv][2] *= al1; oacc[nv][3] *= al1;
        }

        const int src0 = (lane & ~3) | (tg >> 1);
        const int src2 = src0 + 2;
        const bool odd = (tg & 1);
#pragma unroll
        for (int f2 = 0; f2 < 8; f2++) {
            const float x0 = __shfl_sync(0xffffffffu, sacc[f2][0], src0);
            const float x1 = __shfl_sync(0xffffffffu, sacc[f2][1], src0);
            const float x2 = __shfl_sync(0xffffffffu, sacc[f2][0], src2);
            const float x3 = __shfl_sync(0xffffffffu, sacc[f2][1], src2);
            const float y0 = __shfl_sync(0xffffffffu, sacc[f2][2], src0);
            const float y1 = __shfl_sync(0xffffffffu, sacc[f2][3], src0);
            const float y2 = __shfl_sync(0xffffffffu, sacc[f2][2], src2);
            const float y3 = __shfl_sync(0xffffffffu, sacc[f2][3], src2);
            const uint32_t a0 = f2tf32(odd ? x1 : x0);
            const uint32_t a1 = f2tf32(odd ? y1 : y0);
            const uint32_t a2 = f2tf32(odd ? x3 : x2);
            const uint32_t a3 = f2tf32(odd ? y3 : y2);
#pragma unroll
            for (int nv = 0; nv < 16; nv++) {
                const float2 vb = *reinterpret_cast<const float2*>(
                    &Vt[(nv * 8 + g) * VSTR + f2 * 8 + tg * 2]);
                MMA_TF32(oacc[nv][0], oacc[nv][1], oacc[nv][2], oacc[nv][3],
                         a0, a1, a2, a3, f2tf32(vb.x), f2tf32(vb.y));
            }
        }
    }

    const float inv0 = 1.f / l0, inv1 = 1.f / l1;
    const int rga = qbase + r0 + g;
#pragma unroll
    for (int nv = 0; nv < 16; nv++) {
        const int col = h * VDIM + nv * 8 + tg * 2;
        *reinterpret_cast<float2*>(&g_attn[(size_t)rga * (NH * VDIM) + col]) =
            make_float2(round_tf32(oacc[nv][0] * inv0),
                        round_tf32(oacc[nv][1] * inv0));
        *reinterpret_cast<float2*>(&g_attn[(size_t)(rga + 8) * (NH * VDIM) + col]) =
            make_float2(round_tf32(oacc[nv][2] * inv1),
                        round_tf32(oacc[nv][3] * inv1));
    }
}

// ---------------------------------------------------------------------------
// Launch helpers
// ---------------------------------------------------------------------------
static inline void launch_gemm(const float* A, const float* B, float* C,
                               int M, int N, int K)
{
    dim3 grid(N / GBN, M / GBM);
    gemm_tf32_kernel<false><<<grid, 256, GEMM_SMEM>>>(
        A, B, C, nullptr, M, N, N, 0, K);
}
static inline void launch_gemm_split(const float* A, const float* B,
                                     float* C1, float* C2,
                                     int M, int N1, int N2, int K)
{
    const int N = N1 + N2;
    dim3 grid(N / GBN, M / GBM);
    gemm_tf32_kernel<true><<<grid, 256, GEMM_SMEM>>>(
        A, B, C1, C2, M, N, N1, N2, K);
}
static inline void launch_round(const float* src, float* dst, int n)
{
    const int n4 = n / 4;
    int grid = (n4 + 1023) / 1024;
    if (grid > 592) grid = 592;
    round_tf32_kernel<<<grid, 256>>>((const float4*)src, (float4*)dst, n4);
}

extern "C" void kernel_launch(void* const* d_in, const int* in_sizes, int n_in,
                              void* d_out, int out_size)
{
    const float* x         = (const float*)d_in[0];
    const float* w_q_down  = (const float*)d_in[1];
    const float* q_norm_w  = (const float*)d_in[2];
    const float* w_q_up    = (const float*)d_in[3];
    const float* w_kv_down = (const float*)d_in[4];
    const float* kv_norm_w = (const float*)d_in[5];
    const float* w_kv_up   = (const float*)d_in[6];
    const float* w_o       = (const float*)d_in[7];
    float* out = (float*)d_out;

    float *cq, *q, *kv, *ckv, *kvup, *attn;
    float *xr, *wqkvd, *wqu, *wkvu, *wo;
    cudaGetSymbolAddress((void**)&cq,    g_cq);
    cudaGetSymbolAddress((void**)&q,     g_q);
    cudaGetSymbolAddress((void**)&kv,    g_kv);
    cudaGetSymbolAddress((void**)&ckv,   g_ckv);
    cudaGetSymbolAddress((void**)&kvup,  g_kvup);
    cudaGetSymbolAddress((void**)&attn,  g_attn);
    cudaGetSymbolAddress((void**)&xr,    g_x);
    cudaGetSymbolAddress((void**)&wqkvd, g_wqkvd);
    cudaGetSymbolAddress((void**)&wqu,   g_wqu);
    cudaGetSymbolAddress((void**)&wkvu,  g_wkvu);
    cudaGetSymbolAddress((void**)&wo,    g_wo);

    cudaFuncSetAttribute(attn_mma_kernel,
                         cudaFuncAttributeMaxDynamicSharedMemorySize,
                         ATT_SMEM_BYTES);
    cudaFuncSetAttribute(gemm_tf32_kernel<false>,
                         cudaFuncAttributeMaxDynamicSharedMemorySize, GEMM_SMEM);
    cudaFuncSetAttribute(gemm_tf32_kernel<true>,
                         cudaFuncAttributeMaxDynamicSharedMemorySize, GEMM_SMEM);

    // 0. tf32 pre-rounding (kv_down weights appended after q_down weights)
    launch_round(x,         xr,                 SEQ * DIM);
    launch_round(w_q_down,  wqkvd,              QR * DIM);
    launch_round(w_kv_down, wqkvd + QR * DIM,   (KVR + ROPE_D) * DIM);
    launch_round(w_q_up,    wqu,                NH * QKD * QR);
    launch_round(w_kv_up,   wkvu,               NH * KVUP_D * KVR);
    launch_round(w_o,       wo,                 DIM * NH * VDIM);

    // 1. [c_q_pre | kv] = x @ [w_q_down; w_kv_down].T   (fused, split output)
    launch_gemm_split(xr, wqkvd, cq, kv, SEQ, QR, KVR + ROPE_D, DIM);
    // 2. c_q = rmsnorm(c_q_pre), tf32-rounded (in place)
    rmsnorm_kernel<<<SEQ, 256>>>(cq, cq, q_norm_w, QR, QR, QR);
    // 3. q = c_q @ w_q_up.T                     [2048, 3072]
    launch_gemm(cq, wqu, q, SEQ, NH * QKD, QR);
    // 4. c_kv = rmsnorm(kv[:, :512]), tf32-rounded
    rmsnorm_kernel<<<SEQ, 256>>>(kv, ckv, kv_norm_w, KVR, KVR + ROPE_D, KVR);
    // 5. RoPE tables + applications
    rope_tables_kernel<<<(SEQ * 32 + 255) / 256, 256>>>();
    rope_q_kernel<<<(SEQ * NH * 32 + 255) / 256, 256>>>();
    rope_k_kernel<<<(SEQ * 32 + 255) / 256, 256>>>();
    // 6. kv_up = c_kv @ w_kv_up.T               [2048, 4096]
    launch_gemm(ckv, wkvu, kvup, SEQ, NH * KVUP_D, KVR);
    // 7. tensor-core causal attention -> g_attn [2048, 2048]
    attn_mma_kernel<<<dim3(SEQ / 128, NH), 256, ATT_SMEM_BYTES>>>();
    // 8. out = attn @ w_o.T                     [2048, 2048]
    launch_gemm(attn, wo, out, SEQ, DIM, NH * VDIM);
}

// round 7
// speedup vs baseline: 1.3279x; 1.3279x over previous
#include <cuda_runtime.h>
#include <cuda_fp16.h>
#include <math.h>
#include <stdint.h>

// ---------------------------------------------------------------------------
// Problem constants
// ---------------------------------------------------------------------------
constexpr int SEQ    = 2048;
constexpr int DIM    = 2048;
constexpr int NH     = 16;
constexpr int QR     = 1536;
constexpr int KVR    = 512;
constexpr int ROPE_D = 64;
constexpr int NOPE   = 128;
constexpr int VDIM   = 128;
constexpr int QKD    = NOPE + ROPE_D;          // 192
constexpr int KVUP_D = NOPE + VDIM;            // 256
constexpr float EPSF = 1e-6f;

// ---------------------------------------------------------------------------
// Scratch (device globals: allocation-free)
// ---------------------------------------------------------------------------
__device__ __align__(256) float  g_cq   [SEQ * QR];            // down-proj out (float)
__device__ __align__(256) __half g_cqh  [SEQ * QR];            // normed, half
__device__ __align__(256) float  g_kv   [SEQ * (KVR + ROPE_D)];
__device__ __align__(256) __half g_ckvh [SEQ * KVR];
__device__ __align__(256) float  g_q    [SEQ * NH * QKD];
__device__ __align__(256) float  g_krope[SEQ * ROPE_D];
__device__ __align__(256) float  g_kvup [SEQ * NH * KVUP_D];
__device__ __align__(256) __half g_attnh[SEQ * NH * VDIM];
__device__ __align__(256) float  g_cos  [SEQ * (ROPE_D / 2)];
__device__ __align__(256) float  g_sin  [SEQ * (ROPE_D / 2)];
// half operand copies
__device__ __align__(256) __half g_xh   [SEQ * DIM];
__device__ __align__(256) __half g_wqkvdh[(QR + KVR + ROPE_D) * DIM];
__device__ __align__(256) __half g_wquh [NH * QKD * QR];
__device__ __align__(256) __half g_wkvuh[NH * KVUP_D * KVR];
__device__ __align__(256) __half g_woh  [DIM * NH * VDIM];

// ---------------------------------------------------------------------------
// helpers
// ---------------------------------------------------------------------------
__device__ __forceinline__ uint32_t f2tf32(float f) {
    uint32_t u;
    asm("cvt.rna.tf32.f32 %0, %1;" : "=r"(u) : "f"(f));
    return u;
}

#define MMA_TF32(D0,D1,D2,D3,A0,A1,A2,A3,B0,B1)                              \
    asm volatile(                                                            \
        "mma.sync.aligned.m16n8k8.row.col.f32.tf32.tf32.f32 "                \
        "{%0,%1,%2,%3},{%4,%5,%6,%7},{%8,%9},{%0,%1,%2,%3};"                 \
        : "+f"(D0), "+f"(D1), "+f"(D2), "+f"(D3)                             \
        : "r"(A0), "r"(A1), "r"(A2), "r"(A3), "r"(B0), "r"(B1))

#define MMA_F16(D0,D1,D2,D3,A0,A1,A2,A3,B0,B1)                               \
    asm volatile(                                                            \
        "mma.sync.aligned.m16n8k16.row.col.f32.f16.f16.f32 "                 \
        "{%0,%1,%2,%3},{%4,%5,%6,%7},{%8,%9},{%0,%1,%2,%3};"                 \
        : "+f"(D0), "+f"(D1), "+f"(D2), "+f"(D3)                             \
        : "r"(A0), "r"(A1), "r"(A2), "r"(A3), "r"(B0), "r"(B1))

// ---------------------------------------------------------------------------
// float -> half conversion (vectorized)
// ---------------------------------------------------------------------------
struct h4 { __half2 a, b; };

__global__ void __launch_bounds__(256) f2h_kernel(
    const float4* __restrict__ src, h4* __restrict__ dst, int n4)
{
    for (int i = blockIdx.x * 256 + threadIdx.x; i < n4; i += gridDim.x * 256) {
        const float4 v = src[i];
        h4 o;
        o.a = __floats2half2_rn(v.x, v.y);
        o.b = __floats2half2_rn(v.z, v.w);
        dst[i] = o;
    }
}

// ---------------------------------------------------------------------------
// fp16 NT GEMM: C[M,N](f32) = A[M,K](f16) * B[N,K](f16)^T
// 128x64 tiles, K-tile 64 halves, 8 warps each 64x16, m16n8k16.
// 3-stage cp.async pipeline + double-buffered register fragments. 2 CTAs/SM.
// SPLIT: columns [0,N1) -> C, [N1,N) -> C2.
// ---------------------------------------------------------------------------
constexpr int GBM = 128, GBN = 64, GBKH = 64, HSTR = 72; // halves; 8-half pad
constexpr int GTILE_H = (GBM + GBN) * HSTR;              // halves per stage
constexpr int GSTAGES = 3;
constexpr int GEMM_SMEM = GSTAGES * GTILE_H * 2;         // 82944 B

template<bool SPLIT>
__global__ void __launch_bounds__(256, 2) gemm_f16_kernel(
    const __half* __restrict__ A, const __half* __restrict__ B,
    float* __restrict__ C, float* __restrict__ C2,
    int M, int N, int N1, int N2, int K)
{
    extern __shared__ __half smh[];

    const int tid  = threadIdx.x;
    const int warp = tid >> 5;
    const int lane = tid & 31;
    const int g    = lane >> 2;
    const int tg   = lane & 3;
    const int wm   = (warp & 1) * 64;
    const int wn   = (warp >> 1) * 16;
    const int bm0  = blockIdx.y * GBM;
    const int bn0  = blockIdx.x * GBN;

    const uint32_t s0 = (uint32_t)__cvta_generic_to_shared(smh);

    auto load_tiles = [&](int slot, int k0) {
        const uint32_t sA = s0 + slot * (GTILE_H * 2);
        const uint32_t sB = sA + GBM * HSTR * 2;
        // A: 128 rows x 8 chunks(16B=8 halves) = 1024 chunks
#pragma unroll
        for (int i = 0; i < 4; i++) {
            const int c   = tid + i * 256;
            const int row = c >> 3;
            const int seg = c & 7;
            const uint32_t da = sA + (row * HSTR + seg * 8) * 2;
            const __half* ga = A + (size_t)(bm0 + row) * K + k0 + seg * 8;
            asm volatile("cp.async.cg.shared.global [%0], [%1], 16;"
                         :: "r"(da), "l"(ga));
        }
        // B: 64 rows x 8 chunks = 512 chunks
#pragma unroll
        for (int i = 0; i < 2; i++) {
            const int c   = tid + i * 256;
            const int row = c >> 3;
            const int seg = c & 7;
            const int rb  = bn0 + row;
            const int ok  = (rb < N) ? 16 : 0;
            const __half* gb = B + (size_t)(ok ? rb : 0) * K + k0 + seg * 8;
            const uint32_t db = sB + (row * HSTR + seg * 8) * 2;
            asm volatile("cp.async.cg.shared.global [%0], [%1], 16, %2;"
                         :: "r"(db), "l"(gb), "r"(ok));
        }
    };

    float acc[4][2][4];
#pragma unroll
    for (int mt = 0; mt < 4; mt++)
#pragma unroll
        for (int nt = 0; nt < 2; nt++)
#pragma unroll
            for (int v = 0; v < 4; v++) acc[mt][nt][v] = 0.f;

    const int nk = K / GBKH;

#pragma unroll
    for (int s = 0; s < GSTAGES - 1; s++) {
        if (s < nk) load_tiles(s, s * GBKH);
        asm volatile("cp.async.commit_group;");
    }

    uint32_t af[2][4][4], bf[2][2][2];

    // word layout: row stride = 36 words; k16-step s16 -> +8 words
    auto load_frags = [&](int b, const uint32_t* sa32, const uint32_t* sb32,
                          int s16) {
        const int ko = s16 * 8 + tg;
#pragma unroll
        for (int mt = 0; mt < 4; mt++) {
            const int r = wm + mt * 16 + g;
            af[b][mt][0] = sa32[r       * 36 + ko];      // rows g,   k 2tg..+1
            af[b][mt][1] = sa32[(r + 8) * 36 + ko];      // rows g+8
            af[b][mt][2] = sa32[r       * 36 + ko + 4];  // k 2tg+8..+9
            af[b][mt][3] = sa32[(r + 8) * 36 + ko + 4];
        }
#pragma unroll
        for (int nt = 0; nt < 2; nt++) {
            const int rn = wn + nt * 8 + g;
            bf[b][nt][0] = sb32[rn * 36 + ko];
            bf[b][nt][1] = sb32[rn * 36 + ko + 4];
        }
    };

    for (int kt = 0; kt < nk; kt++) {
        asm volatile("cp.async.wait_group %0;" :: "n"(GSTAGES - 2));
        __syncthreads();

        if (kt + GSTAGES - 1 < nk)
            load_tiles((kt + GSTAGES - 1) % GSTAGES, (kt + GSTAGES - 1) * GBKH);
        asm volatile("cp.async.commit_group;");

        const __half* sa = smh + (kt % GSTAGES) * GTILE_H;
        const uint32_t* sa32 = reinterpret_cast<const uint32_t*>(sa);
        const uint32_t* sb32 = reinterpret_cast<const uint32_t*>(sa + GBM * HSTR);

        load_frags(0, sa32, sb32, 0);
#pragma unroll
        for (int s16 = 0; s16 < GBKH / 16; s16++) {
            if (s16 + 1 < GBKH / 16)
                load_frags((s16 + 1) & 1, sa32, sb32, s16 + 1);
            const int b = s16 & 1;
#pragma unroll
            for (int mt = 0; mt < 4; mt++)
#pragma unroll
                for (int nt = 0; nt < 2; nt++)
                    MMA_F16(acc[mt][nt][0], acc[mt][nt][1],
                            acc[mt][nt][2], acc[mt][nt][3],
                            af[b][mt][0], af[b][mt][1],
                            af[b][mt][2], af[b][mt][3],
                            bf[b][nt][0], bf[b][nt][1]);
        }
    }

    float* Cb; int Nw, c0;
    if (SPLIT && bn0 >= N1) { Cb = C2; Nw = N2; c0 = bn0 - N1; }
    else                    { Cb = C;  Nw = SPLIT ? N1 : N; c0 = bn0; }

#pragma unroll
    for (int mt = 0; mt < 4; mt++) {
        const int r0 = bm0 + wm + mt * 16 + g;
#pragma unroll
        for (int nt = 0; nt < 2; nt++) {
            const int cc = c0 + wn + nt * 8 + tg * 2;
            if (cc < Nw) {
                *reinterpret_cast<float2*>(&Cb[(size_t)r0 * Nw + cc]) =
                    make_float2(acc[mt][nt][0], acc[mt][nt][1]);
                *reinterpret_cast<float2*>(&Cb[(size_t)(r0 + 8) * Nw + cc]) =
                    make_float2(acc[mt][nt][2], acc[mt][nt][3]);
            }
        }
    }
}

// ---------------------------------------------------------------------------
// RMSNorm — half output
// ---------------------------------------------------------------------------
__global__ void __launch_bounds__(256) rmsnorm_kernel(
    const float* __restrict__ src, __half* __restrict__ dst,
    const float* __restrict__ w, int R, int sstride, int dstride)
{
    const int row = blockIdx.x;
    const float* s = src + (size_t)row * sstride;
    __half* d = dst + (size_t)row * dstride;

    float sum = 0.f;
    for (int i = threadIdx.x; i < R; i += 256) {
        float v = s[i];
        sum = fmaf(v, v, sum);
    }
    __shared__ float red[8];
#pragma unroll
    for (int o = 16; o; o >>= 1) sum += __shfl_down_sync(0xffffffffu, sum, o);
    if ((threadIdx.x & 31) == 0) red[threadIdx.x >> 5] = sum;
    __syncthreads();
    if (threadIdx.x < 8) {
        float v = red[threadIdx.x];
#pragma unroll
        for (int o = 4; o; o >>= 1) v += __shfl_down_sync(0xffu, v, o);
        if (threadIdx.x == 0) red[0] = v;
    }
    __syncthreads();
    const float mean = red[0] / (float)R;
    const float r = rsqrtf(mean + EPSF);
    for (int i = threadIdx.x; i < R; i += 256)
        d[i] = __float2half_rn(s[i] * r * w[i]);
}

// ---------------------------------------------------------------------------
// RoPE
// ---------------------------------------------------------------------------
__global__ void rope_tables_kernel()
{
    const int idx = blockIdx.x * blockDim.x + threadIdx.x;
    if (idx >= SEQ * (ROPE_D / 2)) return;
    const int t = idx / (ROPE_D / 2);
    const int i = idx % (ROPE_D / 2);
    const double freq = pow(500000.0, -(double)i / 32.0);
    const float ang = (float)t * (float)freq;
    g_cos[idx] = cosf(ang);
    g_sin[idx] = sinf(ang);
}

__global__ void rope_q_kernel()
{
    const int idx = blockIdx.x * blockDim.x + threadIdx.x;
    if (idx >= SEQ * NH * (ROPE_D / 2)) return;
    const int i  = idx & 31;
    const int th = idx >> 5;
    const int h  = th % NH;
    const int t  = th / NH;
    const float c = g_cos[t * 32 + i];
    const float s = g_sin[t * 32 + i];
    float* p = g_q + (size_t)t * (NH * QKD) + h * QKD + NOPE + 2 * i;
    const float e = p[0], o = p[1];
    p[0] = e * c - o * s;
    p[1] = o * c + e * s;
}

__global__ void rope_k_kernel()
{
    const int idx = blockIdx.x * blockDim.x + threadIdx.x;
    if (idx >= SEQ * (ROPE_D / 2)) return;
    const int i = idx & 31;
    const int t = idx >> 5;
    const float c = g_cos[t * 32 + i];
    const float s = g_sin[t * 32 + i];
    const float* src = g_kv + (size_t)t * (KVR + ROPE_D) + KVR + 2 * i;
    const float e = src[0], o = src[1];
    g_krope[t * ROPE_D + 2 * i]     = e * c - o * s;
    g_krope[t * ROPE_D + 2 * i + 1] = o * c + e * s;
}

// ---------------------------------------------------------------------------
// Tensor-core causal flash attention (tf32, unchanged core; half output)
// ---------------------------------------------------------------------------
constexpr int QSTR = 200, VSTR = 72;
constexpr int ATT_SMEM_BYTES = (128 * QSTR + 64 * QSTR + 128 * VSTR) * 4;

__device__ __forceinline__ int kperm(int j) {
    return (j & 3) * 2 + (j >> 2);
}

__global__ void __launch_bounds__(256) attn_mma_kernel()
{
    extern __shared__ float sm[];
    float* Qs = sm;                     // [128][200]
    float* Ks = Qs + 128 * QSTR;        // [64][200]
    float* Vt = Ks + 64 * QSTR;         // [128][72]

    const int tid  = threadIdx.x;
    const int warp = tid >> 5;
    const int lane = tid & 31;
    const int g    = lane >> 2;
    const int tg   = lane & 3;
    const int bx   = blockIdx.x;
    const int qt   = (bx & 1) ? (15 - (bx >> 1)) : (bx >> 1);
    const int h    = blockIdx.y;
    const int qbase = qt * 128;
    const int r0   = warp * 16;
    const float scale = 0.07216878364870322f;  // 1/sqrt(192)

    for (int idx = tid; idx < 128 * 192; idx += 256) {
        const int r = idx / 192, d = idx % 192;
        const int pos = (d & ~7) + kperm(d & 7);
        Qs[r * QSTR + pos] =
            g_q[(size_t)(qbase + r) * (NH * QKD) + h * QKD + d] * scale;
    }

    float sacc[8][4];
    float oacc[16][4];
#pragma unroll
    for (int nv = 0; nv < 16; nv++)
#pragma unroll
        for (int v = 0; v < 4; v++) oacc[nv][v] = 0.f;
    float m0 = -INFINITY, m1 = -INFINITY, l0 = 0.f, l1 = 0.f;

    const int nkt = 2 * qt + 2;
    for (int kt = 0; kt < nkt; kt++) {
        const int kbase = kt * 64;
        __syncthreads();

        for (int idx = tid; idx < 64 * 192; idx += 256) {
            const int r = idx / 192, d = idx % 192;
            const int pos = (d & ~7) + kperm(d & 7);
            const float v = (d < NOPE)
                ? g_kvup[(size_t)(kbase + r) * (NH * KVUP_D) + h * KVUP_D + d]
                : g_krope[(size_t)(kbase + r) * ROPE_D + (d - NOPE)];
            Ks[r * QSTR + pos] = v;
        }
        for (int idx = tid; idx < 64 * 128; idx += 256) {
            const int r = idx >> 7, dv = idx & 127;
            const int pos = (r & ~7) + kperm(r & 7);
            Vt[dv * VSTR + pos] =
                g_kvup[(size_t)(kbase + r) * (NH * KVUP_D) + h * KVUP_D + NOPE + dv];
        }
        __syncthreads();

#pragma unroll
        for (int nf = 0; nf < 8; nf++)
#pragma unroll
            for (int v = 0; v < 4; v++) sacc[nf][v] = 0.f;

#pragma unroll
        for (int f = 0; f < 24; f++) {
            const float2 qa = *reinterpret_cast<const float2*>(
                &Qs[(r0 + g) * QSTR + f * 8 + tg * 2]);
            const float2 qb = *reinterpret_cast<const float2*>(
                &Qs[(r0 + g + 8) * QSTR + f * 8 + tg * 2]);
            const uint32_t a0 = f2tf32(qa.x), a1 = f2tf32(qb.x);
            const uint32_t a2 = f2tf32(qa.y), a3 = f2tf32(qb.y);
#pragma unroll
            for (int nf = 0; nf < 8; nf++) {
                const float2 kb = *reinterpret_cast<const float2*>(
                    &Ks[(nf * 8 + g) * QSTR + f * 8 + tg * 2]);
                MMA_TF32(sacc[nf][0], sacc[nf][1], sacc[nf][2], sacc[nf][3],
                         a0, a1, a2, a3, f2tf32(kb.x), f2tf32(kb.y));
            }
        }

        const int rg  = qbase + r0 + g;
        if (kbase + 63 > rg) {
#pragma unroll
            for (int nf = 0; nf < 8; nf++) {
                const int c0 = kbase + nf * 8 + tg * 2;
                if (c0     > rg)     sacc[nf][0] = -INFINITY;
                if (c0 + 1 > rg)     sacc[nf][1] = -INFINITY;
                if (c0     > rg + 8) sacc[nf][2] = -INFINITY;
                if (c0 + 1 > rg + 8) sacc[nf][3] = -INFINITY;
            }
        }

        float t0 = -INFINITY, t1 = -INFINITY;
#pragma unroll
        for (int nf = 0; nf < 8; nf++) {
            t0 = fmaxf(t0, fmaxf(sacc[nf][0], sacc[nf][1]));
            t1 = fmaxf(t1, fmaxf(sacc[nf][2], sacc[nf][3]));
        }
        t0 = fmaxf(t0, __shfl_xor_sync(0xffffffffu, t0, 1));
        t0 = fmaxf(t0, __shfl_xor_sync(0xffffffffu, t0, 2));
        t1 = fmaxf(t1, __shfl_xor_sync(0xffffffffu, t1, 1));
        t1 = fmaxf(t1, __shfl_xor_sync(0xffffffffu, t1, 2));
        const float nm0 = fmaxf(m0, t0), nm1 = fmaxf(m1, t1);
        const float al0 = __expf(m0 - nm0), al1 = __expf(m1 - nm1);
        m0 = nm0; m1 = nm1;

        float rs0 = 0.f, rs1 = 0.f;
#pragma unroll
        for (int nf = 0; nf < 8; nf++) {
            sacc[nf][0] = __expf(sacc[nf][0] - nm0);
            sacc[nf][1] = __expf(sacc[nf][1] - nm0);
            sacc[nf][2] = __expf(sacc[nf][2] - nm1);
            sacc[nf][3] = __expf(sacc[nf][3] - nm1);
            rs0 += sacc[nf][0] + sacc[nf][1];
            rs1 += sacc[nf][2] + sacc[nf][3];
        }
        rs0 += __shfl_xor_sync(0xffffffffu, rs0, 1);
        rs0 += __shfl_xor_sync(0xffffffffu, rs0, 2);
        rs1 += __shfl_xor_sync(0xffffffffu, rs1, 1);
        rs1 += __shfl_xor_sync(0xffffffffu, rs1, 2);
        l0 = l0 * al0 + rs0;
        l1 = l1 * al1 + rs1;

#pragma unroll
        for (int nv = 0; nv < 16; nv++) {
            oacc[nv][0] *= al0; oacc[nv][1] *= al0;
            oacc[nv][2] *= al1; oacc[nv][3] *= al1;
        }

        const int src0 = (lane & ~3) | (tg >> 1);
        const int src2 = src0 + 2;
        const bool odd = (tg & 1);
#pragma unroll
        for (int f2 = 0; f2 < 8; f2++) {
            const float x0 = __shfl_sync(0xffffffffu, sacc[f2][0], src0);
            const float x1 = __shfl_sync(0xffffffffu, sacc[f2][1], src0);
            const float x2 = __shfl_sync(0xffffffffu, sacc[f2][0], src2);
            const float x3 = __shfl_sync(0xffffffffu, sacc[f2][1], src2);
            const float y0 = __shfl_sync(0xffffffffu, sacc[f2][2], src0);
            const float y1 = __shfl_sync(0xffffffffu, sacc[f2][3], src0);
            const float y2 = __shfl_sync(0xffffffffu, sacc[f2][2], src2);
            const float y3 = __shfl_sync(0xffffffffu, sacc[f2][3], src2);
            const uint32_t a0 = f2tf32(odd ? x1 : x0);
            const uint32_t a1 = f2tf32(odd ? y1 : y0);
            const uint32_t a2 = f2tf32(odd ? x3 : x2);
            const uint32_t a3 = f2tf32(odd ? y3 : y2);
#pragma unroll
            for (int nv = 0; nv < 16; nv++) {
                const float2 vb = *reinterpret_cast<const float2*>(
                    &Vt[(nv * 8 + g) * VSTR + f2 * 8 + tg * 2]);
                MMA_TF32(oacc[nv][0], oacc[nv][1], oacc[nv][2], oacc[nv][3],
                         a0, a1, a2, a3, f2tf32(vb.x), f2tf32(vb.y));
            }
        }
    }

    const float inv0 = 1.f / l0, inv1 = 1.f / l1;
    const int rga = qbase + r0 + g;
#pragma unroll
    for (int nv = 0; nv < 16; nv++) {
        const int col = h * VDIM + nv * 8 + tg * 2;
        *reinterpret_cast<__half2*>(&g_attnh[(size_t)rga * (NH * VDIM) + col]) =
            __floats2half2_rn(oacc[nv][0] * inv0, oacc[nv][1] * inv0);
        *reinterpret_cast<__half2*>(&g_attnh[(size_t)(rga + 8) * (NH * VDIM) + col]) =
            __floats2half2_rn(oacc[nv][2] * inv1, oacc[nv][3] * inv1);
    }
}

// ---------------------------------------------------------------------------
// Launch helpers
// ---------------------------------------------------------------------------
static inline void launch_gemm(const __half* A, const __half* B, float* C,
                               int M, int N, int K)
{
    dim3 grid(N / GBN, M / GBM);
    gemm_f16_kernel<false><<<grid, 256, GEMM_SMEM>>>(
        A, B, C, nullptr, M, N, N, 0, K);
}
static inline void launch_gemm_split(const __half* A, const __half* B,
                                     float* C1, float* C2,
                                     int M, int N1, int N2, int K)
{
    const int N = N1 + N2;
    dim3 grid(N / GBN, M / GBM);
    gemm_f16_kernel<true><<<grid, 256, GEMM_SMEM>>>(
        A, B, C1, C2, M, N, N1, N2, K);
}
static inline void launch_f2h(const float* src, __half* dst, int n)
{
    const int n4 = n / 4;
    int grid = (n4 + 1023) / 1024;
    if (grid > 592) grid = 592;
    f2h_kernel<<<grid, 256>>>((const float4*)src, (h4*)dst, n4);
}

extern "C" void kernel_launch(void* const* d_in, const int* in_sizes, int n_in,
                              void* d_out, int out_size)
{
    const float* x         = (const float*)d_in[0];
    const float* w_q_down  = (const float*)d_in[1];
    const float* q_norm_w  = (const float*)d_in[2];
    const float* w_q_up    = (const float*)d_in[3];
    const float* w_kv_down = (const float*)d_in[4];
    const float* kv_norm_w = (const float*)d_in[5];
    const float* w_kv_up   = (const float*)d_in[6];
    const float* w_o       = (const float*)d_in[7];
    float* out = (float*)d_out;

    float *cq, *kv, *q, *kvup;
    __half *cqh, *ckvh, *attnh, *xh, *wqkvdh, *wquh, *wkvuh, *woh;
    cudaGetSymbolAddress((void**)&cq,     g_cq);
    cudaGetSymbolAddress((void**)&cqh,    g_cqh);
    cudaGetSymbolAddress((void**)&kv,     g_kv);
    cudaGetSymbolAddress((void**)&ckvh,   g_ckvh);
    cudaGetSymbolAddress((void**)&q,      g_q);
    cudaGetSymbolAddress((void**)&kvup,   g_kvup);
    cudaGetSymbolAddress((void**)&attnh,  g_attnh);
    cudaGetSymbolAddress((void**)&xh,     g_xh);
    cudaGetSymbolAddress((void**)&wqkvdh, g_wqkvdh);
    cudaGetSymbolAddress((void**)&wquh,   g_wquh);
    cudaGetSymbolAddress((void**)&wkvuh,  g_wkvuh);
    cudaGetSymbolAddress((void**)&woh,    g_woh);

    cudaFuncSetAttribute(attn_mma_kernel,
                         cudaFuncAttributeMaxDynamicSharedMemorySize,
                         ATT_SMEM_BYTES);
    cudaFuncSetAttribute(gemm_f16_kernel<false>,
                         cudaFuncAttributeMaxDynamicSharedMemorySize, GEMM_SMEM);
    cudaFuncSetAttribute(gemm_f16_kernel<true>,
                         cudaFuncAttributeMaxDynamicSharedMemorySize, GEMM_SMEM);

    // 0. half conversion of x and all weights (kv_down appended after q_down)
    launch_f2h(x,         xh,                SEQ * DIM);
    launch_f2h(w_q_down,  wqkvdh,            QR * DIM);
    launch_f2h(w_kv_down, wqkvdh + QR * DIM, (KVR + ROPE_D) * DIM);
    launch_f2h(w_q_up,    wquh,              NH * QKD * QR);
    launch_f2h(w_kv_up,   wkvuh,             NH * KVUP_D * KVR);
    launch_f2h(w_o,       woh,               DIM * NH * VDIM);

    // 1. [c_q_pre | kv] = x @ [w_q_down; w_kv_down].T  (fused, split output)
    launch_gemm_split(xh, wqkvdh, cq, kv, SEQ, QR, KVR + ROPE_D, DIM);
    // 2. c_q = rmsnorm(c_q_pre) -> half
    rmsnorm_kernel<<<SEQ, 256>>>(cq, cqh, q_norm_w, QR, QR, QR);
    // 3. q = c_q @ w_q_up.T                     [2048, 3072]
    launch_gemm(cqh, wquh, q, SEQ, NH * QKD, QR);
    // 4. c_kv = rmsnorm(kv[:, :512]) -> half
    rmsnorm_kernel<<<SEQ, 256>>>(kv, ckvh, kv_norm_w, KVR, KVR + ROPE_D, KVR);
    // 5. RoPE
    rope_tables_kernel<<<(SEQ * 32 + 255) / 256, 256>>>();
    rope_q_kernel<<<(SEQ * NH * 32 + 255) / 256, 256>>>();
    rope_k_kernel<<<(SEQ * 32 + 255) / 256, 256>>>();
    // 6. kv_up = c_kv @ w_kv_up.T               [2048, 4096]
    launch_gemm(ckvh, wkvuh, kvup, SEQ, NH * KVUP_D, KVR);
    // 7. causal attention -> g_attnh (half)
    attn_mma_kernel<<<dim3(SEQ / 128, NH), 256, ATT_SMEM_BYTES>>>();
    // 8. out = attn @ w_o.T                     [2048, 2048]
    launch_gemm(attnh, woh, out, SEQ, DIM, NH * VDIM);
}

// round 8
// speedup vs baseline: 1.8299x; 1.3780x over previous
#include <cuda_runtime.h>
#include <cuda_fp16.h>
#include <math.h>
#include <stdint.h>

// ---------------------------------------------------------------------------
// Problem constants
// ---------------------------------------------------------------------------
constexpr int SEQ    = 2048;
constexpr int DIM    = 2048;
constexpr int NH     = 16;
constexpr int QR     = 1536;
constexpr int KVR    = 512;
constexpr int ROPE_D = 64;
constexpr int NOPE   = 128;
constexpr int VDIM   = 128;
constexpr int QKD    = NOPE + ROPE_D;          // 192
constexpr int KVUP_D = NOPE + VDIM;            // 256
constexpr float EPSF = 1e-6f;

// ---------------------------------------------------------------------------
// Scratch (device globals: allocation-free)
// ---------------------------------------------------------------------------
__device__ __align__(256) float  g_cq   [SEQ * QR];
__device__ __align__(256) __half g_cqh  [SEQ * QR];
__device__ __align__(256) float  g_kv   [SEQ * (KVR + ROPE_D)];
__device__ __align__(256) __half g_ckvh [SEQ * KVR];
__device__ __align__(256) float  g_q    [SEQ * NH * QKD];
__device__ __align__(256) float  g_krope[SEQ * ROPE_D];
__device__ __align__(256) float  g_kvup [SEQ * NH * KVUP_D];
__device__ __align__(256) __half g_attnh[SEQ * NH * VDIM];
__device__ __align__(256) float  g_cos  [SEQ * (ROPE_D / 2)];
__device__ __align__(256) float  g_sin  [SEQ * (ROPE_D / 2)];
// half operand copies
__device__ __align__(256) __half g_xh   [SEQ * DIM];
__device__ __align__(256) __half g_wqkvdh[(QR + KVR + ROPE_D) * DIM];
__device__ __align__(256) __half g_wquh [NH * QKD * QR];
__device__ __align__(256) __half g_wkvuh[NH * KVUP_D * KVR];
__device__ __align__(256) __half g_woh  [DIM * NH * VDIM];

// ---------------------------------------------------------------------------
// helpers
// ---------------------------------------------------------------------------
__device__ __forceinline__ uint32_t packh2(float a, float b) {
    __half2 h = __floats2half2_rn(a, b);
    return *reinterpret_cast<uint32_t*>(&h);
}

#define MMA_F16(D0,D1,D2,D3,A0,A1,A2,A3,B0,B1)                               \
    asm volatile(                                                            \
        "mma.sync.aligned.m16n8k16.row.col.f32.f16.f16.f32 "                 \
        "{%0,%1,%2,%3},{%4,%5,%6,%7},{%8,%9},{%0,%1,%2,%3};"                 \
        : "+f"(D0), "+f"(D1), "+f"(D2), "+f"(D3)                             \
        : "r"(A0), "r"(A1), "r"(A2), "r"(A3), "r"(B0), "r"(B1))

#define LDSM_X4(R0,R1,R2,R3,ADDR)                                            \
    asm volatile(                                                            \
        "ldmatrix.sync.aligned.m8n8.x4.shared.b16 {%0,%1,%2,%3}, [%4];"      \
        : "=r"(R0), "=r"(R1), "=r"(R2), "=r"(R3) : "r"(ADDR))

// ---------------------------------------------------------------------------
// float -> half conversion (vectorized)
// ---------------------------------------------------------------------------
struct h4 { __half2 a, b; };

__global__ void __launch_bounds__(256) f2h_kernel(
    const float4* __restrict__ src, h4* __restrict__ dst, int n4)
{
    for (int i = blockIdx.x * 256 + threadIdx.x; i < n4; i += gridDim.x * 256) {
        const float4 v = src[i];
        h4 o;
        o.a = __floats2half2_rn(v.x, v.y);
        o.b = __floats2half2_rn(v.z, v.w);
        dst[i] = o;
    }
}

// ---------------------------------------------------------------------------
// fp16 NT GEMM: C[M,N](f32) = A[M,K](f16) * B[N,K](f16)^T
// 128x64 tiles, K-tile 64 halves, 8 warps each 64x16, m16n8k16.
// ldmatrix fragment loads (5 per k16 step). 3-stage cp.async. 2 CTAs/SM.
// ---------------------------------------------------------------------------
constexpr int GBM = 128, GBN = 64, GBKH = 64, HSTR = 72;
constexpr int GTILE_H = (GBM + GBN) * HSTR;
constexpr int GSTAGES = 3;
constexpr int GEMM_SMEM = GSTAGES * GTILE_H * 2;

template<bool SPLIT>
__global__ void __launch_bounds__(256, 2) gemm_f16_kernel(
    const __half* __restrict__ A, const __half* __restrict__ B,
    float* __restrict__ C, float* __restrict__ C2,
    int M, int N, int N1, int N2, int K)
{
    extern __shared__ __half smh[];

    const int tid  = threadIdx.x;
    const int warp = tid >> 5;
    const int lane = tid & 31;
    const int g    = lane >> 2;
    const int tg   = lane & 3;
    const int wm   = (warp & 1) * 64;
    const int wn   = (warp >> 1) * 16;
    const int bm0  = blockIdx.y * GBM;
    const int bn0  = blockIdx.x * GBN;

    const uint32_t s0 = (uint32_t)__cvta_generic_to_shared(smh);

    auto load_tiles = [&](int slot, int k0) {
        const uint32_t sA = s0 + slot * (GTILE_H * 2);
        const uint32_t sB = sA + GBM * HSTR * 2;
#pragma unroll
        for (int i = 0; i < 4; i++) {
            const int c   = tid + i * 256;
            const int row = c >> 3;
            const int seg = c & 7;
            const uint32_t da = sA + (row * HSTR + seg * 8) * 2;
            const __half* ga = A + (size_t)(bm0 + row) * K + k0 + seg * 8;
            asm volatile("cp.async.cg.shared.global [%0], [%1], 16;"
                         :: "r"(da), "l"(ga));
        }
#pragma unroll
        for (int i = 0; i < 2; i++) {
            const int c   = tid + i * 256;
            const int row = c >> 3;
            const int seg = c & 7;
            const int rb  = bn0 + row;
            const int ok  = (rb < N) ? 16 : 0;
            const __half* gb = B + (size_t)(ok ? rb : 0) * K + k0 + seg * 8;
            const uint32_t db = sB + (row * HSTR + seg * 8) * 2;
            asm volatile("cp.async.cg.shared.global [%0], [%1], 16, %2;"
                         :: "r"(db), "l"(gb), "r"(ok));
        }
    };

    float acc[4][2][4];
#pragma unroll
    for (int mt = 0; mt < 4; mt++)
#pragma unroll
        for (int nt = 0; nt < 2; nt++)
#pragma unroll
            for (int v = 0; v < 4; v++) acc[mt][nt][v] = 0.f;

    const int nk = K / GBKH;

#pragma unroll
    for (int s = 0; s < GSTAGES - 1; s++) {
        if (s < nk) load_tiles(s, s * GBKH);
        asm volatile("cp.async.commit_group;");
    }

    // ldmatrix per-lane address components (bytes, within a stage)
    const int aRow = lane & 15;
    const int aK8  = (lane >> 4) * 8;                     // halves
    uint32_t aOff[4];
#pragma unroll
    for (int mt = 0; mt < 4; mt++)
        aOff[mt] = ((wm + mt * 16 + aRow) * HSTR + aK8) * 2;
    const int bRow = wn + (lane & 7) + ((lane & 16) ? 8 : 0);
    const uint32_t bOff = (bRow * HSTR + (lane & 8)) * 2 + GBM * HSTR * 2;

    uint32_t af[2][4][4], bf[2][2][2];

    auto load_frags = [&](int b, uint32_t sbase, int s16) {
        const uint32_t kb = sbase + s16 * 32;             // 16 halves = 32 B
#pragma unroll
        for (int mt = 0; mt < 4; mt++)
            LDSM_X4(af[b][mt][0], af[b][mt][1], af[b][mt][2], af[b][mt][3],
                    kb + aOff[mt]);
        LDSM_X4(bf[b][0][0], bf[b][0][1], bf[b][1][0], bf[b][1][1],
                kb + bOff);
    };

    for (int kt = 0; kt < nk; kt++) {
        asm volatile("cp.async.wait_group %0;" :: "n"(GSTAGES - 2));
        __syncthreads();

        if (kt + GSTAGES - 1 < nk)
            load_tiles((kt + GSTAGES - 1) % GSTAGES, (kt + GSTAGES - 1) * GBKH);
        asm volatile("cp.async.commit_group;");

        const uint32_t sbase = s0 + (kt % GSTAGES) * (GTILE_H * 2);

        load_frags(0, sbase, 0);
#pragma unroll
        for (int s16 = 0; s16 < GBKH / 16; s16++) {
            if (s16 + 1 < GBKH / 16)
                load_frags((s16 + 1) & 1, sbase, s16 + 1);
            const int b = s16 & 1;
#pragma unroll
            for (int mt = 0; mt < 4; mt++)
#pragma unroll
                for (int nt = 0; nt < 2; nt++)
                    MMA_F16(acc[mt][nt][0], acc[mt][nt][1],
                            acc[mt][nt][2], acc[mt][nt][3],
                            af[b][mt][0], af[b][mt][1],
                            af[b][mt][2], af[b][mt][3],
                            bf[b][nt][0], bf[b][nt][1]);
        }
    }

    float* Cb; int Nw, c0;
    if (SPLIT && bn0 >= N1) { Cb = C2; Nw = N2; c0 = bn0 - N1; }
    else                    { Cb = C;  Nw = SPLIT ? N1 : N; c0 = bn0; }

#pragma unroll
    for (int mt = 0; mt < 4; mt++) {
        const int r0 = bm0 + wm + mt * 16 + g;
#pragma unroll
        for (int nt = 0; nt < 2; nt++) {
            const int cc = c0 + wn + nt * 8 + tg * 2;
            if (cc < Nw) {
                *reinterpret_cast<float2*>(&Cb[(size_t)r0 * Nw + cc]) =
                    make_float2(acc[mt][nt][0], acc[mt][nt][1]);
                *reinterpret_cast<float2*>(&Cb[(size_t)(r0 + 8) * Nw + cc]) =
                    make_float2(acc[mt][nt][2], acc[mt][nt][3]);
            }
        }
    }
}

// ---------------------------------------------------------------------------
// RMSNorm — half output
// ---------------------------------------------------------------------------
__global__ void __launch_bounds__(256) rmsnorm_kernel(
    const float* __restrict__ src, __half* __restrict__ dst,
    const float* __restrict__ w, int R, int sstride, int dstride)
{
    const int row = blockIdx.x;
    const float* s = src + (size_t)row * sstride;
    __half* d = dst + (size_t)row * dstride;

    float sum = 0.f;
    for (int i = threadIdx.x; i < R; i += 256) {
        float v = s[i];
        sum = fmaf(v, v, sum);
    }
    __shared__ float red[8];
#pragma unroll
    for (int o = 16; o; o >>= 1) sum += __shfl_down_sync(0xffffffffu, sum, o);
    if ((threadIdx.x & 31) == 0) red[threadIdx.x >> 5] = sum;
    __syncthreads();
    if (threadIdx.x < 8) {
        float v = red[threadIdx.x];
#pragma unroll
        for (int o = 4; o; o >>= 1) v += __shfl_down_sync(0xffu, v, o);
        if (threadIdx.x == 0) red[0] = v;
    }
    __syncthreads();
    const float mean = red[0] / (float)R;
    const float r = rsqrtf(mean + EPSF);
    for (int i = threadIdx.x; i < R; i += 256)
        d[i] = __float2half_rn(s[i] * r * w[i]);
}

// ---------------------------------------------------------------------------
// RoPE
// ---------------------------------------------------------------------------
__global__ void rope_tables_kernel()
{
    const int idx = blockIdx.x * blockDim.x + threadIdx.x;
    if (idx >= SEQ * (ROPE_D / 2)) return;
    const int t = idx / (ROPE_D / 2);
    const int i = idx % (ROPE_D / 2);
    const double freq = pow(500000.0, -(double)i / 32.0);
    const float ang = (float)t * (float)freq;
    g_cos[idx] = cosf(ang);
    g_sin[idx] = sinf(ang);
}

__global__ void rope_q_kernel()
{
    const int idx = blockIdx.x * blockDim.x + threadIdx.x;
    if (idx >= SEQ * NH * (ROPE_D / 2)) return;
    const int i  = idx & 31;
    const int th = idx >> 5;
    const int h  = th % NH;
    const int t  = th / NH;
    const float c = g_cos[t * 32 + i];
    const float s = g_sin[t * 32 + i];
    float* p = g_q + (size_t)t * (NH * QKD) + h * QKD + NOPE + 2 * i;
    const float e = p[0], o = p[1];
    p[0] = e * c - o * s;
    p[1] = o * c + e * s;
}

__global__ void rope_k_kernel()
{
    const int idx = blockIdx.x * blockDim.x + threadIdx.x;
    if (idx >= SEQ * (ROPE_D / 2)) return;
    const int i = idx & 31;
    const int t = idx >> 5;
    const float c = g_cos[t * 32 + i];
    const float s = g_sin[t * 32 + i];
    const float* src = g_kv + (size_t)t * (KVR + ROPE_D) + KVR + 2 * i;
    const float e = src[0], o = src[1];
    g_krope[t * ROPE_D + 2 * i]     = e * c - o * s;
    g_krope[t * ROPE_D + 2 * i + 1] = o * c + e * s;
}

// ---------------------------------------------------------------------------
// fp16 tensor-core causal flash attention.
// CTA: 128 q-rows x 1 head, 8 warps x 16 rows, 64-wide K tiles, m16n8k16.
// ldmatrix fragment loads; P C-fragment maps directly to fp16 A-fragment
// for P@V (no shuffles). Softmax in fp32.
// ---------------------------------------------------------------------------
constexpr int QSH = 200;   // halves stride for Q/K rows (400B ≡ 16 mod 128)
constexpr int VSH = 72;    // halves stride for V^T rows (144B)
constexpr int ATT_SMEM_BYTES = (128 * QSH + 64 * QSH + 128 * VSH) * 2; // 95232

__global__ void __launch_bounds__(256) attn_f16_kernel()
{
    extern __shared__ __half smh[];
    __half* Qs = smh;               // [128][200]
    __half* Ks = Qs + 128 * QSH;    // [64][200]
    __half* Vt = Ks + 64 * QSH;     // [128][72]  V^T (vdim-major)

    const int tid  = threadIdx.x;
    const int warp = tid >> 5;
    const int lane = tid & 31;
    const int g    = lane >> 2;
    const int tg   = lane & 3;
    const int bx   = blockIdx.x;
    const int qt   = (bx & 1) ? (15 - (bx >> 1)) : (bx >> 1);
    const int h    = blockIdx.y;
    const int qbase = qt * 128;
    const int r0   = warp * 16;
    const float scale = 0.07216878364870322f;  // 1/sqrt(192)

    const uint32_t q_sm = (uint32_t)__cvta_generic_to_shared(Qs);
    const uint32_t k_sm = (uint32_t)__cvta_generic_to_shared(Ks);
    const uint32_t v_sm = (uint32_t)__cvta_generic_to_shared(Vt);

    // ldmatrix per-lane address components
    const int aRow = lane & 15;
    const int aK8  = (lane >> 4) * 8;
    const uint32_t qa_off = q_sm + ((r0 + aRow) * QSH + aK8) * 2;
    const int bRowL = (lane & 7) + ((lane & 16) ? 8 : 0);
    const int bK8   = lane & 8;

    // Q tile (scale folded)
    for (int idx = tid; idx < 128 * 192; idx += 256) {
        const int r = idx / 192, d = idx % 192;
        Qs[r * QSH + d] = __float2half_rn(
            g_q[(size_t)(qbase + r) * (NH * QKD) + h * QKD + d] * scale);
    }

    float sacc[8][4];
    float oacc[16][4];
#pragma unroll
    for (int nv = 0; nv < 16; nv++)
#pragma unroll
        for (int v = 0; v < 4; v++) oacc[nv][v] = 0.f;
    float m0 = -INFINITY, m1 = -INFINITY, l0 = 0.f, l1 = 0.f;

    const int nkt = 2 * qt + 2;
    for (int kt = 0; kt < nkt; kt++) {
        const int kbase = kt * 64;
        __syncthreads();

        for (int idx = tid; idx < 64 * 192; idx += 256) {
            const int r = idx / 192, d = idx % 192;
            const float v = (d < NOPE)
                ? g_kvup[(size_t)(kbase + r) * (NH * KVUP_D) + h * KVUP_D + d]
                : g_krope[(size_t)(kbase + r) * ROPE_D + (d - NOPE)];
            Ks[r * QSH + d] = __float2half_rn(v);
        }
        for (int idx = tid; idx < 64 * 128; idx += 256) {
            const int r = idx >> 7, dv = idx & 127;
            Vt[dv * VSH + r] = __float2half_rn(
                g_kvup[(size_t)(kbase + r) * (NH * KVUP_D) + h * KVUP_D + NOPE + dv]);
        }
        __syncthreads();

        // ---- S = (scaled Q) K^T : 12 k16 steps ------------------------
#pragma unroll
        for (int nf = 0; nf < 8; nf++)
#pragma unroll
            for (int v = 0; v < 4; v++) sacc[nf][v] = 0.f;

#pragma unroll
        for (int s16 = 0; s16 < 12; s16++) {
            uint32_t a0, a1, a2, a3;
            LDSM_X4(a0, a1, a2, a3, qa_off + s16 * 32);
#pragma unroll
            for (int nfp = 0; nfp < 4; nfp++) {
                uint32_t b0, b1, b2, b3;
                LDSM_X4(b0, b1, b2, b3,
                        k_sm + ((nfp * 16 + bRowL) * QSH + bK8) * 2 + s16 * 32);
                MMA_F16(sacc[2*nfp][0], sacc[2*nfp][1],
                        sacc[2*nfp][2], sacc[2*nfp][3],
                        a0, a1, a2, a3, b0, b1);
                MMA_F16(sacc[2*nfp+1][0], sacc[2*nfp+1][1],
                        sacc[2*nfp+1][2], sacc[2*nfp+1][3],
                        a0, a1, a2, a3, b2, b3);
            }
        }

        // ---- causal mask (diagonal tiles only) ------------------------
        const int rg = qbase + r0 + g;
        if (kbase + 63 > rg) {
#pragma unroll
            for (int nf = 0; nf < 8; nf++) {
                const int c0 = kbase + nf * 8 + tg * 2;
                if (c0     > rg)     sacc[nf][0] = -INFINITY;
                if (c0 + 1 > rg)     sacc[nf][1] = -INFINITY;
                if (c0     > rg + 8) sacc[nf][2] = -INFINITY;
                if (c0 + 1 > rg + 8) sacc[nf][3] = -INFINITY;
            }
        }

        // ---- online softmax (fp32) ------------------------------------
        float t0 = -INFINITY, t1 = -INFINITY;
#pragma unroll
        for (int nf = 0; nf < 8; nf++) {
            t0 = fmaxf(t0, fmaxf(sacc[nf][0], sacc[nf][1]));
            t1 = fmaxf(t1, fmaxf(sacc[nf][2], sacc[nf][3]));
        }
        t0 = fmaxf(t0, __shfl_xor_sync(0xffffffffu, t0, 1));
        t0 = fmaxf(t0, __shfl_xor_sync(0xffffffffu, t0, 2));
        t1 = fmaxf(t1, __shfl_xor_sync(0xffffffffu, t1, 1));
        t1 = fmaxf(t1, __shfl_xor_sync(0xffffffffu, t1, 2));
        const float nm0 = fmaxf(m0, t0), nm1 = fmaxf(m1, t1);
        const float al0 = __expf(m0 - nm0), al1 = __expf(m1 - nm1);
        m0 = nm0; m1 = nm1;

        float rs0 = 0.f, rs1 = 0.f;
#pragma unroll
        for (int nf = 0; nf < 8; nf++) {
            sacc[nf][0] = __expf(sacc[nf][0] - nm0);
            sacc[nf][1] = __expf(sacc[nf][1] - nm0);
            sacc[nf][2] = __expf(sacc[nf][2] - nm1);
            sacc[nf][3] = __expf(sacc[nf][3] - nm1);
            rs0 += sacc[nf][0] + sacc[nf][1];
            rs1 += sacc[nf][2] + sacc[nf][3];
        }
        rs0 += __shfl_xor_sync(0xffffffffu, rs0, 1);
        rs0 += __shfl_xor_sync(0xffffffffu, rs0, 2);
        rs1 += __shfl_xor_sync(0xffffffffu, rs1, 1);
        rs1 += __shfl_xor_sync(0xffffffffu, rs1, 2);
        l0 = l0 * al0 + rs0;
        l1 = l1 * al1 + rs1;

#pragma unroll
        for (int nv = 0; nv < 16; nv++) {
            oacc[nv][0] *= al0; oacc[nv][1] *= al0;
            oacc[nv][2] *= al1; oacc[nv][3] *= al1;
        }

        // ---- O += P @ V : P C-frag maps directly to fp16 A-frag --------
#pragma unroll
        for (int s = 0; s < 4; s++) {
            const uint32_t pa0 = packh2(sacc[2*s][0],   sacc[2*s][1]);
            const uint32_t pa1 = packh2(sacc[2*s][2],   sacc[2*s][3]);
            const uint32_t pa2 = packh2(sacc[2*s+1][0], sacc[2*s+1][1]);
            const uint32_t pa3 = packh2(sacc[2*s+1][2], sacc[2*s+1][3]);
#pragma unroll
            for (int nvp = 0; nvp < 8; nvp++) {
                uint32_t b0, b1, b2, b3;
                LDSM_X4(b0, b1, b2, b3,
                        v_sm + ((nvp * 16 + bRowL) * VSH + bK8) * 2 + s * 32);
                MMA_F16(oacc[2*nvp][0], oacc[2*nvp][1],
                        oacc[2*nvp][2], oacc[2*nvp][3],
                        pa0, pa1, pa2, pa3, b0, b1);
                MMA_F16(oacc[2*nvp+1][0], oacc[2*nvp+1][1],
                        oacc[2*nvp+1][2], oacc[2*nvp+1][3],
                        pa0, pa1, pa2, pa3, b2, b3);
            }
        }
    }

    // ---- epilogue ------------------------------------------------------
    const float inv0 = 1.f / l0, inv1 = 1.f / l1;
    const int rga = qbase + r0 + g;
#pragma unroll
    for (int nv = 0; nv < 16; nv++) {
        const int col = h * VDIM + nv * 8 + tg * 2;
        *reinterpret_cast<__half2*>(&g_attnh[(size_t)rga * (NH * VDIM) + col]) =
            __floats2half2_rn(oacc[nv][0] * inv0, oacc[nv][1] * inv0);
        *reinterpret_cast<__half2*>(&g_attnh[(size_t)(rga + 8) * (NH * VDIM) + col]) =
            __floats2half2_rn(oacc[nv][2] * inv1, oacc[nv][3] * inv1);
    }
}

// ---------------------------------------------------------------------------
// Launch helpers
// ---------------------------------------------------------------------------
static inline void launch_gemm(const __half* A, const __half* B, float* C,
                               int M, int N, int K)
{
    dim3 grid(N / GBN, M / GBM);
    gemm_f16_kernel<false><<<grid, 256, GEMM_SMEM>>>(
        A, B, C, nullptr, M, N, N, 0, K);
}
static inline void launch_gemm_split(const __half* A, const __half* B,
                                     float* C1, float* C2,
                                     int M, int N1, int N2, int K)
{
    const int N = N1 + N2;
    dim3 grid(N / GBN, M / GBM);
    gemm_f16_kernel<true><<<grid, 256, GEMM_SMEM>>>(
        A, B, C1, C2, M, N, N1, N2, K);
}
static inline void launch_f2h(const float* src, __half* dst, int n)
{
    const int n4 = n / 4;
    int grid = (n4 + 1023) / 1024;
    if (grid > 592) grid = 592;
    f2h_kernel<<<grid, 256>>>((const float4*)src, (h4*)dst, n4);
}

extern "C" void kernel_launch(void* const* d_in, const int* in_sizes, int n_in,
                              void* d_out, int out_size)
{
    const float* x         = (const float*)d_in[0];
    const float* w_q_down  = (const float*)d_in[1];
    const float* q_norm_w  = (const float*)d_in[2];
    const float* w_q_up    = (const float*)d_in[3];
    const float* w_kv_down = (const float*)d_in[4];
    const float* kv_norm_w = (const float*)d_in[5];
    const float* w_kv_up   = (const float*)d_in[6];
    const float* w_o       = (const float*)d_in[7];
    float* out = (float*)d_out;

    float *cq, *kv, *q, *kvup;
    __half *cqh, *ckvh, *attnh, *xh, *wqkvdh, *wquh, *wkvuh, *woh;
    cudaGetSymbolAddress((void**)&cq,     g_cq);
    cudaGetSymbolAddress((void**)&cqh,    g_cqh);
    cudaGetSymbolAddress((void**)&kv,     g_kv);
    cudaGetSymbolAddress((void**)&ckvh,   g_ckvh);
    cudaGetSymbolAddress((void**)&q,      g_q);
    cudaGetSymbolAddress((void**)&kvup,   g_kvup);
    cudaGetSymbolAddress((void**)&attnh,  g_attnh);
    cudaGetSymbolAddress((void**)&xh,     g_xh);
    cudaGetSymbolAddress((void**)&wqkvdh, g_wqkvdh);
    cudaGetSymbolAddress((void**)&wquh,   g_wquh);
    cudaGetSymbolAddress((void**)&wkvuh,  g_wkvuh);
    cudaGetSymbolAddress((void**)&woh,    g_woh);

    cudaFuncSetAttribute(attn_f16_kernel,
                         cudaFuncAttributeMaxDynamicSharedMemorySize,
                         ATT_SMEM_BYTES);
    cudaFuncSetAttribute(gemm_f16_kernel<false>,
                         cudaFuncAttributeMaxDynamicSharedMemorySize, GEMM_SMEM);
    cudaFuncSetAttribute(gemm_f16_kernel<true>,
                         cudaFuncAttributeMaxDynamicSharedMemorySize, GEMM_SMEM);

    // 0. half conversion of x and all weights
    launch_f2h(x,         xh,                SEQ * DIM);
    launch_f2h(w_q_down,  wqkvdh,            QR * DIM);
    launch_f2h(w_kv_down, wqkvdh + QR * DIM, (KVR + ROPE_D) * DIM);
    launch_f2h(w_q_up,    wquh,              NH * QKD * QR);
    launch_f2h(w_kv_up,   wkvuh,             NH * KVUP_D * KVR);
    launch_f2h(w_o,       woh,               DIM * NH * VDIM);

    // 1. [c_q_pre | kv] = x @ [w_q_down; w_kv_down].T  (fused, split output)
    launch_gemm_split(xh, wqkvdh, cq, kv, SEQ, QR, KVR + ROPE_D, DIM);
    // 2. c_q = rmsnorm(c_q_pre) -> half
    rmsnorm_kernel<<<SEQ, 256>>>(cq, cqh, q_norm_w, QR, QR, QR);
    // 3. q = c_q @ w_q_up.T                     [2048, 3072]
    launch_gemm(cqh, wquh, q, SEQ, NH * QKD, QR);
    // 4. c_kv = rmsnorm(kv[:, :512]) -> half
    rmsnorm_kernel<<<SEQ, 256>>>(kv, ckvh, kv_norm_w, KVR, KVR + ROPE_D, KVR);
    // 5. RoPE
    rope_tables_kernel<<<(SEQ * 32 + 255) / 256, 256>>>();
    rope_q_kernel<<<(SEQ * NH * 32 + 255) / 256, 256>>>();
    rope_k_kernel<<<(SEQ * 32 + 255) / 256, 256>>>();
    // 6. kv_up = c_kv @ w_kv_up.T               [2048, 4096]
    launch_gemm(ckvh, wkvuh, kvup, SEQ, NH * KVUP_D, KVR);
    // 7. fp16 causal attention -> g_attnh
    attn_f16_kernel<<<dim3(SEQ / 128, NH), 256, ATT_SMEM_BYTES>>>();
    // 8. out = attn @ w_o.T                     [2048, 2048]
    launch_gemm(attnh, woh, out, SEQ, DIM, NH * VDIM);
}

// round 10
// speedup vs baseline: 2.0106x; 1.0988x over previous
#include <cuda_runtime.h>
#include <cuda_fp16.h>
#include <math.h>
#include <stdint.h>

// ---------------------------------------------------------------------------
// Problem constants
// ---------------------------------------------------------------------------
constexpr int SEQ    = 2048;
constexpr int DIM    = 2048;
constexpr int NH     = 16;
constexpr int QR     = 1536;
constexpr int KVR    = 512;
constexpr int ROPE_D = 64;
constexpr int NOPE   = 128;
constexpr int VDIM   = 128;
constexpr int QKD    = NOPE + ROPE_D;          // 192
constexpr int KVUP_D = NOPE + VDIM;            // 256
constexpr float EPSF = 1e-6f;

// ---------------------------------------------------------------------------
// Scratch (device globals: allocation-free)
// ---------------------------------------------------------------------------
__device__ __align__(256) float  g_cq   [SEQ * QR];
__device__ __align__(256) __half g_cqh  [SEQ * QR];
__device__ __align__(256) float  g_kv   [SEQ * (KVR + ROPE_D)];
__device__ __align__(256) __half g_ckvh [SEQ * KVR];
__device__ __align__(256) float  g_q    [SEQ * NH * QKD];
__device__ __align__(256) float  g_krope[SEQ * ROPE_D];
__device__ __align__(256) float  g_kvup [SEQ * NH * KVUP_D];
__device__ __align__(256) __half g_attnh[SEQ * NH * VDIM];
__device__ __align__(256) float  g_cos  [SEQ * (ROPE_D / 2)];
__device__ __align__(256) float  g_sin  [SEQ * (ROPE_D / 2)];
// half operand copies
__device__ __align__(256) __half g_xh   [SEQ * DIM];
__device__ __align__(256) __half g_wqkvdh[(QR + KVR + ROPE_D) * DIM];
__device__ __align__(256) __half g_wquh [NH * QKD * QR];
__device__ __align__(256) __half g_wkvuh[NH * KVUP_D * KVR];
__device__ __align__(256) __half g_woh  [DIM * NH * VDIM];

// ---------------------------------------------------------------------------
// helpers
// ---------------------------------------------------------------------------
__device__ __forceinline__ uint32_t packh2(float a, float b) {
    __half2 h = __floats2half2_rn(a, b);
    return *reinterpret_cast<uint32_t*>(&h);
}

#define MMA_F16(D0,D1,D2,D3,A0,A1,A2,A3,B0,B1)                               \
    asm volatile(                                                            \
        "mma.sync.aligned.m16n8k16.row.col.f32.f16.f16.f32 "                 \
        "{%0,%1,%2,%3},{%4,%5,%6,%7},{%8,%9},{%0,%1,%2,%3};"                 \
        : "+f"(D0), "+f"(D1), "+f"(D2), "+f"(D3)                             \
        : "r"(A0), "r"(A1), "r"(A2), "r"(A3), "r"(B0), "r"(B1))

#define LDSM_X4(R0,R1,R2,R3,ADDR)                                            \
    asm volatile(                                                            \
        "ldmatrix.sync.aligned.m8n8.x4.shared.b16 {%0,%1,%2,%3}, [%4];"      \
        : "=r"(R0), "=r"(R1), "=r"(R2), "=r"(R3) : "r"(ADDR))

// ---------------------------------------------------------------------------
// float -> half conversion (vectorized)
// ---------------------------------------------------------------------------
struct h4 { __half2 a, b; };

__global__ void __launch_bounds__(256) f2h_kernel(
    const float4* __restrict__ src, h4* __restrict__ dst, int n4)
{
    for (int i = blockIdx.x * 256 + threadIdx.x; i < n4; i += gridDim.x * 256) {
        const float4 v = src[i];
        h4 o;
        o.a = __floats2half2_rn(v.x, v.y);
        o.b = __floats2half2_rn(v.z, v.w);
        dst[i] = o;
    }
}

// ---------------------------------------------------------------------------
// fp16 NT GEMM: C[M,N](f32) = A[M,K](f16) * B[N,K](f16)^T
// 128x128 CTA tile, K-tile 64 halves, 8 warps each 64x32, m16n8k16.
// ldmatrix frag loads (6 per k16 step, 16 MMAs). 3-stage cp.async. 2 CTAs/SM.
// Ragged N handled by load predicate + epilogue guard.
// SPLIT: columns [0,N1) -> C (width N1), [N1,N) -> C2 (width N2).
// ---------------------------------------------------------------------------
constexpr int GBM = 128, GBN = 128, GBKH = 64, HSTR = 72;
constexpr int GTILE_H = (GBM + GBN) * HSTR;              // halves per stage
constexpr int GSTAGES = 3;
constexpr int GEMM_SMEM = GSTAGES * GTILE_H * 2;         // 110592 B
constexpr int A_OFF_B  = GBM * HSTR * 2;                 // B region byte offset

template<bool SPLIT>
__global__ void __launch_bounds__(256, 2) gemm_f16_kernel(
    const __half* __restrict__ A, const __half* __restrict__ B,
    float* __restrict__ C, float* __restrict__ C2,
    int M, int N, int N1, int N2, int K)
{
    extern __shared__ __half smh[];

    const int tid  = threadIdx.x;
    const int warp = tid >> 5;
    const int lane = tid & 31;
    const int g    = lane >> 2;
    const int tg   = lane & 3;
    const int wm   = (warp & 1) * 64;
    const int wn   = (warp >> 1) * 32;
    const int bm0  = blockIdx.y * GBM;
    const int bn0  = blockIdx.x * GBN;

    const uint32_t s0 = (uint32_t)__cvta_generic_to_shared(smh);

    auto load_tiles = [&](int slot, int k0) {
        const uint32_t sA = s0 + slot * (GTILE_H * 2);
        const uint32_t sB = sA + A_OFF_B;
#pragma unroll
        for (int i = 0; i < 4; i++) {          // A: 1024 16B chunks
            const int c   = tid + i * 256;
            const int row = c >> 3;
            const int seg = c & 7;
            const uint32_t da = sA + (row * HSTR + seg * 8) * 2;
            const __half* ga = A + (size_t)(bm0 + row) * K + k0 + seg * 8;
            asm volatile("cp.async.cg.shared.global [%0], [%1], 16;"
                         :: "r"(da), "l"(ga));
        }
#pragma unroll
        for (int i = 0; i < 4; i++) {          // B: 1024 chunks, predicated
            const int c   = tid + i * 256;
            const int row = c >> 3;
            const int seg = c & 7;
            const int rb  = bn0 + row;
            const int ok  = (rb < N) ? 16 : 0;
            const __half* gb = B + (size_t)(ok ? rb : 0) * K + k0 + seg * 8;
            const uint32_t db = sB + (row * HSTR + seg * 8) * 2;
            asm volatile("cp.async.cg.shared.global [%0], [%1], 16, %2;"
                         :: "r"(db), "l"(gb), "r"(ok));
        }
    };

    float acc[4][4][4];
#pragma unroll
    for (int mt = 0; mt < 4; mt++)
#pragma unroll
        for (int nt = 0; nt < 4; nt++)
#pragma unroll
            for (int v = 0; v < 4; v++) acc[mt][nt][v] = 0.f;

    const int nk = K / GBKH;

#pragma unroll
    for (int s = 0; s < GSTAGES - 1; s++) {
        if (s < nk) load_tiles(s, s * GBKH);
        asm volatile("cp.async.commit_group;");
    }

    // ldmatrix per-lane offsets (bytes within a stage)
    const int aRow = lane & 15;
    const int aK8  = (lane >> 4) * 8;
    uint32_t aOff[4];
#pragma unroll
    for (int mt = 0; mt < 4; mt++)
        aOff[mt] = ((wm + mt * 16 + aRow) * HSTR + aK8) * 2;
    const int bRowL = (lane & 7) + ((lane & 16) ? 8 : 0);
    const int bK8   = lane & 8;
    uint32_t bOff[2];
#pragma unroll
    for (int p = 0; p < 2; p++)
        bOff[p] = ((wn + p * 16 + bRowL) * HSTR + bK8) * 2 + A_OFF_B;

    for (int kt = 0; kt < nk; kt++) {
        asm volatile("cp.async.wait_group %0;" :: "n"(GSTAGES - 2));
        __syncthreads();

        if (kt + GSTAGES - 1 < nk)
            load_tiles((kt + GSTAGES - 1) % GSTAGES, (kt + GSTAGES - 1) * GBKH);
        asm volatile("cp.async.commit_group;");

        const uint32_t sbase = s0 + (kt % GSTAGES) * (GTILE_H * 2);

#pragma unroll
        for (int s16 = 0; s16 < GBKH / 16; s16++) {
            const uint32_t kb = sbase + s16 * 32;
            uint32_t af[4][4], bf[4][2];
#pragma unroll
            for (int mt = 0; mt < 4; mt++)
                LDSM_X4(af[mt][0], af[mt][1], af[mt][2], af[mt][3],
                        kb + aOff[mt]);
#pragma unroll
            for (int p = 0; p < 2; p++)
                LDSM_X4(bf[2*p][0], bf[2*p][1], bf[2*p+1][0], bf[2*p+1][1],
                        kb + bOff[p]);
#pragma unroll
            for (int mt = 0; mt < 4; mt++)
#pragma unroll
                for (int nt = 0; nt < 4; nt++)
                    MMA_F16(acc[mt][nt][0], acc[mt][nt][1],
                            acc[mt][nt][2], acc[mt][nt][3],
                            af[mt][0], af[mt][1], af[mt][2], af[mt][3],
                            bf[nt][0], bf[nt][1]);
        }
    }

    float* Cb; int Nw, c0;
    if (SPLIT && bn0 >= N1) { Cb = C2; Nw = N2; c0 = bn0 - N1; }
    else                    { Cb = C;  Nw = SPLIT ? N1 : N; c0 = bn0; }

#pragma unroll
    for (int mt = 0; mt < 4; mt++) {
        const int r0 = bm0 + wm + mt * 16 + g;
#pragma unroll
        for (int nt = 0; nt < 4; nt++) {
            const int cc = c0 + wn + nt * 8 + tg * 2;
            if (cc < Nw) {
                *reinterpret_cast<float2*>(&Cb[(size_t)r0 * Nw + cc]) =
                    make_float2(acc[mt][nt][0], acc[mt][nt][1]);
                *reinterpret_cast<float2*>(&Cb[(size_t)(r0 + 8) * Nw + cc]) =
                    make_float2(acc[mt][nt][2], acc[mt][nt][3]);
            }
        }
    }
}

// ---------------------------------------------------------------------------
// RMSNorm — half output
// ---------------------------------------------------------------------------
__global__ void __launch_bounds__(256) rmsnorm_kernel(
    const float* __restrict__ src, __half* __restrict__ dst,
    const float* __restrict__ w, int R, int sstride, int dstride)
{
    const int row = blockIdx.x;
    const float* s = src + (size_t)row * sstride;
    __half* d = dst + (size_t)row * dstride;

    float sum = 0.f;
    for (int i = threadIdx.x; i < R; i += 256) {
        float v = s[i];
        sum = fmaf(v, v, sum);
    }
    __shared__ float red[8];
#pragma unroll
    for (int o = 16; o; o >>= 1) sum += __shfl_down_sync(0xffffffffu, sum, o);
    if ((threadIdx.x & 31) == 0) red[threadIdx.x >> 5] = sum;
    __syncthreads();
    if (threadIdx.x < 8) {
        float v = red[threadIdx.x];
#pragma unroll
        for (int o = 4; o; o >>= 1) v += __shfl_down_sync(0xffu, v, o);
        if (threadIdx.x == 0) red[0] = v;
    }
    __syncthreads();
    const float mean = red[0] / (float)R;
    const float r = rsqrtf(mean + EPSF);
    for (int i = threadIdx.x; i < R; i += 256)
        d[i] = __float2half_rn(s[i] * r * w[i]);
}

// ---------------------------------------------------------------------------
// RoPE
// ---------------------------------------------------------------------------
__global__ void rope_tables_kernel()
{
    const int idx = blockIdx.x * blockDim.x + threadIdx.x;
    if (idx >= SEQ * (ROPE_D / 2)) return;
    const int t = idx / (ROPE_D / 2);
    const int i = idx % (ROPE_D / 2);
    const double freq = pow(500000.0, -(double)i / 32.0);
    const float ang = (float)t * (float)freq;
    g_cos[idx] = cosf(ang);
    g_sin[idx] = sinf(ang);
}

__global__ void rope_q_kernel()
{
    const int idx = blockIdx.x * blockDim.x + threadIdx.x;
    if (idx >= SEQ * NH * (ROPE_D / 2)) return;
    const int i  = idx & 31;
    const int th = idx >> 5;
    const int h  = th % NH;
    const int t  = th / NH;
    const float c = g_cos[t * 32 + i];
    const float s = g_sin[t * 32 + i];
    float* p = g_q + (size_t)t * (NH * QKD) + h * QKD + NOPE + 2 * i;
    const float e = p[0], o = p[1];
    p[0] = e * c - o * s;
    p[1] = o * c + e * s;
}

__global__ void rope_k_kernel()
{
    const int idx = blockIdx.x * blockDim.x + threadIdx.x;
    if (idx >= SEQ * (ROPE_D / 2)) return;
    const int i = idx & 31;
    const int t = idx >> 5;
    const float c = g_cos[t * 32 + i];
    const float s = g_sin[t * 32 + i];
    const float* src = g_kv + (size_t)t * (KVR + ROPE_D) + KVR + 2 * i;
    const float e = src[0], o = src[1];
    g_krope[t * ROPE_D + 2 * i]     = e * c - o * s;
    g_krope[t * ROPE_D + 2 * i + 1] = o * c + e * s;
}

// ---------------------------------------------------------------------------
// fp16 tensor-core causal flash attention (unchanged from R8)
// ---------------------------------------------------------------------------
constexpr int QSH = 200;
constexpr int VSH = 72;
constexpr int ATT_SMEM_BYTES = (128 * QSH + 64 * QSH + 128 * VSH) * 2;

__global__ void __launch_bounds__(256) attn_f16_kernel()
{
    extern __shared__ __half smh[];
    __half* Qs = smh;               // [128][200]
    __half* Ks = Qs + 128 * QSH;    // [64][200]
    __half* Vt = Ks + 64 * QSH;     // [128][72]

    const int tid  = threadIdx.x;
    const int warp = tid >> 5;
    const int lane = tid & 31;
    const int g    = lane >> 2;
    const int tg   = lane & 3;
    const int bx   = blockIdx.x;
    const int qt   = (bx & 1) ? (15 - (bx >> 1)) : (bx >> 1);
    const int h    = blockIdx.y;
    const int qbase = qt * 128;
    const int r0   = warp * 16;
    const float scale = 0.07216878364870322f;  // 1/sqrt(192)

    const uint32_t q_sm = (uint32_t)__cvta_generic_to_shared(Qs);
    const uint32_t k_sm = (uint32_t)__cvta_generic_to_shared(Ks);
    const uint32_t v_sm = (uint32_t)__cvta_generic_to_shared(Vt);

    const int aRow = lane & 15;
    const int aK8  = (lane >> 4) * 8;
    const uint32_t qa_off = q_sm + ((r0 + aRow) * QSH + aK8) * 2;
    const int bRowL = (lane & 7) + ((lane & 16) ? 8 : 0);
    const int bK8   = lane & 8;

    for (int idx = tid; idx < 128 * 192; idx += 256) {
        const int r = idx / 192, d = idx % 192;
        Qs[r * QSH + d] = __float2half_rn(
            g_q[(size_t)(qbase + r) * (NH * QKD) + h * QKD + d] * scale);
    }

    float sacc[8][4];
    float oacc[16][4];
#pragma unroll
    for (int nv = 0; nv < 16; nv++)
#pragma unroll
        for (int v = 0; v < 4; v++) oacc[nv][v] = 0.f;
    float m0 = -INFINITY, m1 = -INFINITY, l0 = 0.f, l1 = 0.f;

    const int nkt = 2 * qt + 2;
    for (int kt = 0; kt < nkt; kt++) {
        const int kbase = kt * 64;
        __syncthreads();

        for (int idx = tid; idx < 64 * 192; idx += 256) {
            const int r = idx / 192, d = idx % 192;
            const float v = (d < NOPE)
                ? g_kvup[(size_t)(kbase + r) * (NH * KVUP_D) + h * KVUP_D + d]
                : g_krope[(size_t)(kbase + r) * ROPE_D + (d - NOPE)];
            Ks[r * QSH + d] = __float2half_rn(v);
        }
        for (int idx = tid; idx < 64 * 128; idx += 256) {
            const int r = idx >> 7, dv = idx & 127;
            Vt[dv * VSH + r] = __float2half_rn(
                g_kvup[(size_t)(kbase + r) * (NH * KVUP_D) + h * KVUP_D + NOPE + dv]);
        }
        __syncthreads();

#pragma unroll
        for (int nf = 0; nf < 8; nf++)
#pragma unroll
            for (int v = 0; v < 4; v++) sacc[nf][v] = 0.f;

#pragma unroll
        for (int s16 = 0; s16 < 12; s16++) {
            uint32_t a0, a1, a2, a3;
            LDSM_X4(a0, a1, a2, a3, qa_off + s16 * 32);
#pragma unroll
            for (int nfp = 0; nfp < 4; nfp++) {
                uint32_t b0, b1, b2, b3;
                LDSM_X4(b0, b1, b2, b3,
                        k_sm + ((nfp * 16 + bRowL) * QSH + bK8) * 2 + s16 * 32);
                MMA_F16(sacc[2*nfp][0], sacc[2*nfp][1],
                        sacc[2*nfp][2], sacc[2*nfp][3],
                        a0, a1, a2, a3, b0, b1);
                MMA_F16(sacc[2*nfp+1][0], sacc[2*nfp+1][1],
                        sacc[2*nfp+1][2], sacc[2*nfp+1][3],
                        a0, a1, a2, a3, b2, b3);
            }
        }

        const int rg = qbase + r0 + g;
        if (kbase + 63 > rg) {
#pragma unroll
            for (int nf = 0; nf < 8; nf++) {
                const int c0 = kbase + nf * 8 + tg * 2;
                if (c0     > rg)     sacc[nf][0] = -INFINITY;
                if (c0 + 1 > rg)     sacc[nf][1] = -INFINITY;
                if (c0     > rg + 8) sacc[nf][2] = -INFINITY;
                if (c0 + 1 > rg + 8) sacc[nf][3] = -INFINITY;
            }
        }

        float t0 = -INFINITY, t1 = -INFINITY;
#pragma unroll
        for (int nf = 0; nf < 8; nf++) {
            t0 = fmaxf(t0, fmaxf(sacc[nf][0], sacc[nf][1]));
            t1 = fmaxf(t1, fmaxf(sacc[nf][2], sacc[nf][3]));
        }
        t0 = fmaxf(t0, __shfl_xor_sync(0xffffffffu, t0, 1));
        t0 = fmaxf(t0, __shfl_xor_sync(0xffffffffu, t0, 2));
        t1 = fmaxf(t1, __shfl_xor_sync(0xffffffffu, t1, 1));
        t1 = fmaxf(t1, __shfl_xor_sync(0xffffffffu, t1, 2));
        const float nm0 = fmaxf(m0, t0), nm1 = fmaxf(m1, t1);
        const float al0 = __expf(m0 - nm0), al1 = __expf(m1 - nm1);
        m0 = nm0; m1 = nm1;

        float rs0 = 0.f, rs1 = 0.f;
#pragma unroll
        for (int nf = 0; nf < 8; nf++) {
            sacc[nf][0] = __expf(sacc[nf][0] - nm0);
            sacc[nf][1] = __expf(sacc[nf][1] - nm0);
            sacc[nf][2] = __expf(sacc[nf][2] - nm1);
            sacc[nf][3] = __expf(sacc[nf][3] - nm1);
            rs0 += sacc[nf][0] + sacc[nf][1];
            rs1 += sacc[nf][2] + sacc[nf][3];
        }
        rs0 += __shfl_xor_sync(0xffffffffu, rs0, 1);
        rs0 += __shfl_xor_sync(0xffffffffu, rs0, 2);
        rs1 += __shfl_xor_sync(0xffffffffu, rs1, 1);
        rs1 += __shfl_xor_sync(0xffffffffu, rs1, 2);
        l0 = l0 * al0 + rs0;
        l1 = l1 * al1 + rs1;

#pragma unroll
        for (int nv = 0; nv < 16; nv++) {
            oacc[nv][0] *= al0; oacc[nv][1] *= al0;
            oacc[nv][2] *= al1; oacc[nv][3] *= al1;
        }

#pragma unroll
        for (int s = 0; s < 4; s++) {
            const uint32_t pa0 = packh2(sacc[2*s][0],   sacc[2*s][1]);
            const uint32_t pa1 = packh2(sacc[2*s][2],   sacc[2*s][3]);
            const uint32_t pa2 = packh2(sacc[2*s+1][0], sacc[2*s+1][1]);
            const uint32_t pa3 = packh2(sacc[2*s+1][2], sacc[2*s+1][3]);
#pragma unroll
            for (int nvp = 0; nvp < 8; nvp++) {
                uint32_t b0, b1, b2, b3;
                LDSM_X4(b0, b1, b2, b3,
                        v_sm + ((nvp * 16 + bRowL) * VSH + bK8) * 2 + s * 32);
                MMA_F16(oacc[2*nvp][0], oacc[2*nvp][1],
                        oacc[2*nvp][2], oacc[2*nvp][3],
                        pa0, pa1, pa2, pa3, b0, b1);
                MMA_F16(oacc[2*nvp+1][0], oacc[2*nvp+1][1],
                        oacc[2*nvp+1][2], oacc[2*nvp+1][3],
                        pa0, pa1, pa2, pa3, b2, b3);
            }
        }
    }

    const float inv0 = 1.f / l0, inv1 = 1.f / l1;
    const int rga = qbase + r0 + g;
#pragma unroll
    for (int nv = 0; nv < 16; nv++) {
        const int col = h * VDIM + nv * 8 + tg * 2;
        *reinterpret_cast<__half2*>(&g_attnh[(size_t)rga * (NH * VDIM) + col]) =
            __floats2half2_rn(oacc[nv][0] * inv0, oacc[nv][1] * inv0);
        *reinterpret_cast<__half2*>(&g_attnh[(size_t)(rga + 8) * (NH * VDIM) + col]) =
            __floats2half2_rn(oacc[nv][2] * inv1, oacc[nv][3] * inv1);
    }
}

// ---------------------------------------------------------------------------
// Launch helpers
// ---------------------------------------------------------------------------
static inline void launch_gemm(const __half* A, const __half* B, float* C,
                               int M, int N, int K)
{
    dim3 grid((N + GBN - 1) / GBN, M / GBM);
    gemm_f16_kernel<false><<<grid, 256, GEMM_SMEM>>>(
        A, B, C, nullptr, M, N, N, 0, K);
}
static inline void launch_gemm_split(const __half* A, const __half* B,
                                     float* C1, float* C2,
                                     int M, int N1, int N2, int K)
{
    const int N = N1 + N2;
    dim3 grid((N + GBN - 1) / GBN, M / GBM);
    gemm_f16_kernel<true><<<grid, 256, GEMM_SMEM>>>(
        A, B, C1, C2, M, N, N1, N2, K);
}
static inline void launch_f2h(const float* src, __half* dst, int n)
{
    const int n4 = n / 4;
    int grid = (n4 + 1023) / 1024;
    if (grid > 592) grid = 592;
    f2h_kernel<<<grid, 256>>>((const float4*)src, (h4*)dst, n4);
}

extern "C" void kernel_launch(void* const* d_in, const int* in_sizes, int n_in,
                              void* d_out, int out_size)
{
    const float* x         = (const float*)d_in[0];
    const float* w_q_down  = (const float*)d_in[1];
    const float* q_norm_w  = (const float*)d_in[2];
    const float* w_q_up    = (const float*)d_in[3];
    const float* w_kv_down = (const float*)d_in[4];
    const float* kv_norm_w = (const float*)d_in[5];
    const float* w_kv_up   = (const float*)d_in[6];
    const float* w_o       = (const float*)d_in[7];
    float* out = (float*)d_out;

    float *cq, *kv, *q, *kvup;
    __half *cqh, *ckvh, *attnh, *xh, *wqkvdh, *wquh, *wkvuh, *woh;
    cudaGetSymbolAddress((void**)&cq,     g_cq);
    cudaGetSymbolAddress((void**)&cqh,    g_cqh);
    cudaGetSymbolAddress((void**)&kv,     g_kv);
    cudaGetSymbolAddress((void**)&ckvh,   g_ckvh);
    cudaGetSymbolAddress((void**)&q,      g_q);
    cudaGetSymbolAddress((void**)&kvup,   g_kvup);
    cudaGetSymbolAddress((void**)&attnh,  g_attnh);
    cudaGetSymbolAddress((void**)&xh,     g_xh);
    cudaGetSymbolAddress((void**)&wqkvdh, g_wqkvdh);
    cudaGetSymbolAddress((void**)&wquh,   g_wquh);
    cudaGetSymbolAddress((void**)&wkvuh,  g_wkvuh);
    cudaGetSymbolAddress((void**)&woh,    g_woh);

    cudaFuncSetAttribute(attn_f16_kernel,
                         cudaFuncAttributeMaxDynamicSharedMemorySize,
                         ATT_SMEM_BYTES);
    cudaFuncSetAttribute(gemm_f16_kernel<false>,
                         cudaFuncAttributeMaxDynamicSharedMemorySize, GEMM_SMEM);
    cudaFuncSetAttribute(gemm_f16_kernel<true>,
                         cudaFuncAttributeMaxDynamicSharedMemorySize, GEMM_SMEM);

    // 0. half conversion of x and all weights
    launch_f2h(x,         xh,                SEQ * DIM);
    launch_f2h(w_q_down,  wqkvdh,            QR * DIM);
    launch_f2h(w_kv_down, wqkvdh + QR * DIM, (KVR + ROPE_D) * DIM);
    launch_f2h(w_q_up,    wquh,              NH * QKD * QR);
    launch_f2h(w_kv_up,   wkvuh,             NH * KVUP_D * KVR);
    launch_f2h(w_o,       woh,               DIM * NH * VDIM);

    // 1. [c_q_pre | kv] = x @ [w_q_down; w_kv_down].T  (fused, split output)
    launch_gemm_split(xh, wqkvdh, cq, kv, SEQ, QR, KVR + ROPE_D, DIM);
    // 2. c_q = rmsnorm(c_q_pre) -> half
    rmsnorm_kernel<<<SEQ, 256>>>(cq, cqh, q_norm_w, QR, QR, QR);
    // 3. q = c_q @ w_q_up.T                     [2048, 3072]
    launch_gemm(cqh, wquh, q, SEQ, NH * QKD, QR);
    // 4. c_kv = rmsnorm(kv[:, :512]) -> half
    rmsnorm_kernel<<<SEQ, 256>>>(kv, ckvh, kv_norm_w, KVR, KVR + ROPE_D, KVR);
    // 5. RoPE
    rope_tables_kernel<<<(SEQ * 32 + 255) / 256, 256>>>();
    rope_q_kernel<<<(SEQ * NH * 32 + 255) / 256, 256>>>();
    rope_k_kernel<<<(SEQ * 32 + 255) / 256, 256>>>();
    // 6. kv_up = c_kv @ w_kv_up.T               [2048, 4096]
    launch_gemm(ckvh, wkvuh, kvup, SEQ, NH * KVUP_D, KVR);
    // 7. fp16 causal attention -> g_attnh
    attn_f16_kernel<<<dim3(SEQ / 128, NH), 256, ATT_SMEM_BYTES>>>();
    // 8. out = attn @ w_o.T                     [2048, 2048]
    launch_gemm(attnh, woh, out, SEQ, DIM, NH * VDIM);
}

// round 11
// speedup vs baseline: 3.4113x; 1.6966x over previous
#include <cuda_runtime.h>
#include <cuda_fp16.h>
#include <math.h>
#include <stdint.h>

// ---------------------------------------------------------------------------
// Problem constants
// ---------------------------------------------------------------------------
constexpr int SEQ    = 2048;
constexpr int DIM    = 2048;
constexpr int NH     = 16;
constexpr int QR     = 1536;
constexpr int KVR    = 512;
constexpr int ROPE_D = 64;
constexpr int NOPE   = 128;
constexpr int VDIM   = 128;
constexpr int QKD    = NOPE + ROPE_D;          // 192
constexpr int KVUP_D = NOPE + VDIM;            // 256
constexpr float EPSF = 1e-6f;

// ---------------------------------------------------------------------------
// Scratch (device globals: allocation-free) — all-half intermediates
// ---------------------------------------------------------------------------
__device__ __align__(256) __half g_cqh  [SEQ * QR];            // down-proj out / normed
__device__ __align__(256) __half g_kvh  [SEQ * (KVR + ROPE_D)];
__device__ __align__(256) __half g_ckvh [SEQ * KVR];
__device__ __align__(256) __half g_qh   [SEQ * NH * QKD];      // pre-scaled q
__device__ __align__(256) __half g_kropeh[SEQ * ROPE_D];
__device__ __align__(256) __half g_kvuph[SEQ * NH * KVUP_D];   // k_nope | v
__device__ __align__(256) __half g_attnh[SEQ * NH * VDIM];
__device__ __align__(256) float  g_cos  [SEQ * (ROPE_D / 2)];
__device__ __align__(256) float  g_sin  [SEQ * (ROPE_D / 2)];
// half operand copies
__device__ __align__(256) __half g_xh   [SEQ * DIM];
__device__ __align__(256) __half g_wqkvdh[(QR + KVR + ROPE_D) * DIM];
__device__ __align__(256) __half g_wquh [NH * QKD * QR];       // scaled by 1/sqrt(192)
__device__ __align__(256) __half g_wkvuh[NH * KVUP_D * KVR];
__device__ __align__(256) __half g_woh  [DIM * NH * VDIM];

// ---------------------------------------------------------------------------
// helpers
// ---------------------------------------------------------------------------
__device__ __forceinline__ uint32_t packh2(float a, float b) {
    __half2 h = __floats2half2_rn(a, b);
    return *reinterpret_cast<uint32_t*>(&h);
}

#define MMA_F16(D0,D1,D2,D3,A0,A1,A2,A3,B0,B1)                               \
    asm volatile(                                                            \
        "mma.sync.aligned.m16n8k16.row.col.f32.f16.f16.f32 "                 \
        "{%0,%1,%2,%3},{%4,%5,%6,%7},{%8,%9},{%0,%1,%2,%3};"                 \
        : "+f"(D0), "+f"(D1), "+f"(D2), "+f"(D3)                             \
        : "r"(A0), "r"(A1), "r"(A2), "r"(A3), "r"(B0), "r"(B1))

#define LDSM_X4(R0,R1,R2,R3,ADDR)                                            \
    asm volatile(                                                            \
        "ldmatrix.sync.aligned.m8n8.x4.shared.b16 {%0,%1,%2,%3}, [%4];"      \
        : "=r"(R0), "=r"(R1), "=r"(R2), "=r"(R3) : "r"(ADDR))

#define LDSM_X4_T(R0,R1,R2,R3,ADDR)                                          \
    asm volatile(                                                            \
        "ldmatrix.sync.aligned.m8n8.x4.trans.shared.b16 {%0,%1,%2,%3}, [%4];"\
        : "=r"(R0), "=r"(R1), "=r"(R2), "=r"(R3) : "r"(ADDR))

#define CP_ASYNC16(DST,SRC)                                                  \
    asm volatile("cp.async.cg.shared.global [%0], [%1], 16;"                 \
                 :: "r"(DST), "l"(SRC))

// ---------------------------------------------------------------------------
// float -> half conversion (vectorized, optional scale)
// ---------------------------------------------------------------------------
struct h4 { __half2 a, b; };

__global__ void __launch_bounds__(256) f2h_kernel(
    const float4* __restrict__ src, h4* __restrict__ dst, int n4, float scale)
{
    for (int i = blockIdx.x * 256 + threadIdx.x; i < n4; i += gridDim.x * 256) {
        const float4 v = src[i];
        h4 o;
        o.a = __floats2half2_rn(v.x * scale, v.y * scale);
        o.b = __floats2half2_rn(v.z * scale, v.w * scale);
        dst[i] = o;
    }
}

// ---------------------------------------------------------------------------
// fp16 NT GEMM: C[M,N] = A[M,K](f16) * B[N,K](f16)^T
// 128x128 CTA, 8 warps x (64x32), m16n8k16, ldmatrix, 3-stage cp.async.
// HALF_OUT: write __half, else float. SPLIT: cols [0,N1)->C, [N1,N)->C2.
// ---------------------------------------------------------------------------
constexpr int GBM = 128, GBN = 128, GBKH = 64, HSTR = 72;
constexpr int GTILE_H = (GBM + GBN) * HSTR;
constexpr int GSTAGES = 3;
constexpr int GEMM_SMEM = GSTAGES * GTILE_H * 2;
constexpr int A_OFF_B  = GBM * HSTR * 2;

template<bool SPLIT, bool HALF_OUT>
__global__ void __launch_bounds__(256, 2) gemm_f16_kernel(
    const __half* __restrict__ A, const __half* __restrict__ B,
    void* __restrict__ C, void* __restrict__ C2,
    int M, int N, int N1, int N2, int K)
{
    extern __shared__ __half smh[];

    const int tid  = threadIdx.x;
    const int warp = tid >> 5;
    const int lane = tid & 31;
    const int g    = lane >> 2;
    const int tg   = lane & 3;
    const int wm   = (warp & 1) * 64;
    const int wn   = (warp >> 1) * 32;
    const int bm0  = blockIdx.y * GBM;
    const int bn0  = blockIdx.x * GBN;

    const uint32_t s0 = (uint32_t)__cvta_generic_to_shared(smh);

    auto load_tiles = [&](int slot, int k0) {
        const uint32_t sA = s0 + slot * (GTILE_H * 2);
        const uint32_t sB = sA + A_OFF_B;
#pragma unroll
        for (int i = 0; i < 4; i++) {
            const int c   = tid + i * 256;
            const int row = c >> 3;
            const int seg = c & 7;
            const uint32_t da = sA + (row * HSTR + seg * 8) * 2;
            const __half* ga = A + (size_t)(bm0 + row) * K + k0 + seg * 8;
            CP_ASYNC16(da, ga);
        }
#pragma unroll
        for (int i = 0; i < 4; i++) {
            const int c   = tid + i * 256;
            const int row = c >> 3;
            const int seg = c & 7;
            const int rb  = bn0 + row;
            const int ok  = (rb < N) ? 16 : 0;
            const __half* gb = B + (size_t)(ok ? rb : 0) * K + k0 + seg * 8;
            const uint32_t db = sB + (row * HSTR + seg * 8) * 2;
            asm volatile("cp.async.cg.shared.global [%0], [%1], 16, %2;"
                         :: "r"(db), "l"(gb), "r"(ok));
        }
    };

    float acc[4][4][4];
#pragma unroll
    for (int mt = 0; mt < 4; mt++)
#pragma unroll
        for (int nt = 0; nt < 4; nt++)
#pragma unroll
            for (int v = 0; v < 4; v++) acc[mt][nt][v] = 0.f;

    const int nk = K / GBKH;

#pragma unroll
    for (int s = 0; s < GSTAGES - 1; s++) {
        if (s < nk) load_tiles(s, s * GBKH);
        asm volatile("cp.async.commit_group;");
    }

    const int aRow = lane & 15;
    const int aK8  = (lane >> 4) * 8;
    uint32_t aOff[4];
#pragma unroll
    for (int mt = 0; mt < 4; mt++)
        aOff[mt] = ((wm + mt * 16 + aRow) * HSTR + aK8) * 2;
    const int bRowL = (lane & 7) + ((lane & 16) ? 8 : 0);
    const int bK8   = lane & 8;
    uint32_t bOff[2];
#pragma unroll
    for (int p = 0; p < 2; p++)
        bOff[p] = ((wn + p * 16 + bRowL) * HSTR + bK8) * 2 + A_OFF_B;

    for (int kt = 0; kt < nk; kt++) {
        asm volatile("cp.async.wait_group %0;" :: "n"(GSTAGES - 2));
        __syncthreads();

        if (kt + GSTAGES - 1 < nk)
            load_tiles((kt + GSTAGES - 1) % GSTAGES, (kt + GSTAGES - 1) * GBKH);
        asm volatile("cp.async.commit_group;");

        const uint32_t sbase = s0 + (kt % GSTAGES) * (GTILE_H * 2);

#pragma unroll
        for (int s16 = 0; s16 < GBKH / 16; s16++) {
            const uint32_t kb = sbase + s16 * 32;
            uint32_t af[4][4], bf[4][2];
#pragma unroll
            for (int mt = 0; mt < 4; mt++)
                LDSM_X4(af[mt][0], af[mt][1], af[mt][2], af[mt][3],
                        kb + aOff[mt]);
#pragma unroll
            for (int p = 0; p < 2; p++)
                LDSM_X4(bf[2*p][0], bf[2*p][1], bf[2*p+1][0], bf[2*p+1][1],
                        kb + bOff[p]);
#pragma unroll
            for (int mt = 0; mt < 4; mt++)
#pragma unroll
                for (int nt = 0; nt < 4; nt++)
                    MMA_F16(acc[mt][nt][0], acc[mt][nt][1],
                            acc[mt][nt][2], acc[mt][nt][3],
                            af[mt][0], af[mt][1], af[mt][2], af[mt][3],
                            bf[nt][0], bf[nt][1]);
        }
    }

    void* Cbv; int Nw, c0;
    if (SPLIT && bn0 >= N1) { Cbv = C2; Nw = N2; c0 = bn0 - N1; }
    else                    { Cbv = C;  Nw = SPLIT ? N1 : N; c0 = bn0; }

#pragma unroll
    for (int mt = 0; mt < 4; mt++) {
        const int r0 = bm0 + wm + mt * 16 + g;
#pragma unroll
        for (int nt = 0; nt < 4; nt++) {
            const int cc = c0 + wn + nt * 8 + tg * 2;
            if (cc < Nw) {
                if (HALF_OUT) {
                    __half* Ch = (__half*)Cbv;
                    *reinterpret_cast<__half2*>(&Ch[(size_t)r0 * Nw + cc]) =
                        __floats2half2_rn(acc[mt][nt][0], acc[mt][nt][1]);
                    *reinterpret_cast<__half2*>(&Ch[(size_t)(r0 + 8) * Nw + cc]) =
                        __floats2half2_rn(acc[mt][nt][2], acc[mt][nt][3]);
                } else {
                    float* Cf = (float*)Cbv;
                    *reinterpret_cast<float2*>(&Cf[(size_t)r0 * Nw + cc]) =
                        make_float2(acc[mt][nt][0], acc[mt][nt][1]);
                    *reinterpret_cast<float2*>(&Cf[(size_t)(r0 + 8) * Nw + cc]) =
                        make_float2(acc[mt][nt][2], acc[mt][nt][3]);
                }
            }
        }
    }
}

// ---------------------------------------------------------------------------
// RMSNorm — half in, half out (reduction in fp32)
// ---------------------------------------------------------------------------
__global__ void __launch_bounds__(256) rmsnorm_kernel(
    const __half* __restrict__ src, __half* __restrict__ dst,
    const float* __restrict__ w, int R, int sstride, int dstride)
{
    const int row = blockIdx.x;
    const __half* s = src + (size_t)row * sstride;
    __half* d = dst + (size_t)row * dstride;

    float sum = 0.f;
    for (int i = threadIdx.x; i < R; i += 256) {
        float v = __half2float(s[i]);
        sum = fmaf(v, v, sum);
    }
    __shared__ float red[8];
#pragma unroll
    for (int o = 16; o; o >>= 1) sum += __shfl_down_sync(0xffffffffu, sum, o);
    if ((threadIdx.x & 31) == 0) red[threadIdx.x >> 5] = sum;
    __syncthreads();
    if (threadIdx.x < 8) {
        float v = red[threadIdx.x];
#pragma unroll
        for (int o = 4; o; o >>= 1) v += __shfl_down_sync(0xffu, v, o);
        if (threadIdx.x == 0) red[0] = v;
    }
    __syncthreads();
    const float mean = red[0] / (float)R;
    const float r = rsqrtf(mean + EPSF);
    for (int i = threadIdx.x; i < R; i += 256)
        d[i] = __float2half_rn(__half2float(s[i]) * r * w[i]);
}

// ---------------------------------------------------------------------------
// RoPE (half in/out, fp32 rotation)
// ---------------------------------------------------------------------------
__global__ void rope_tables_kernel()
{
    const int idx = blockIdx.x * blockDim.x + threadIdx.x;
    if (idx >= SEQ * (ROPE_D / 2)) return;
    const int t = idx / (ROPE_D / 2);
    const int i = idx % (ROPE_D / 2);
    const double freq = pow(500000.0, -(double)i / 32.0);
    const float ang = (float)t * (float)freq;
    g_cos[idx] = cosf(ang);
    g_sin[idx] = sinf(ang);
}

__global__ void rope_q_kernel()
{
    const int idx = blockIdx.x * blockDim.x + threadIdx.x;
    if (idx >= SEQ * NH * (ROPE_D / 2)) return;
    const int i  = idx & 31;
    const int th = idx >> 5;
    const int h  = th % NH;
    const int t  = th / NH;
    const float c = g_cos[t * 32 + i];
    const float s = g_sin[t * 32 + i];
    __half2* p = reinterpret_cast<__half2*>(
        g_qh + (size_t)t * (NH * QKD) + h * QKD + NOPE + 2 * i);
    const float2 eo = __half22float2(*p);
    *p = __floats2half2_rn(eo.x * c - eo.y * s, eo.y * c + eo.x * s);
}

__global__ void rope_k_kernel()
{
    const int idx = blockIdx.x * blockDim.x + threadIdx.x;
    if (idx >= SEQ * (ROPE_D / 2)) return;
    const int i = idx & 31;
    const int t = idx >> 5;
    const float c = g_cos[t * 32 + i];
    const float s = g_sin[t * 32 + i];
    const __half2 src = *reinterpret_cast<const __half2*>(
        g_kvh + (size_t)t * (KVR + ROPE_D) + KVR + 2 * i);
    const float2 eo = __half22float2(src);
    *reinterpret_cast<__half2*>(g_kropeh + t * ROPE_D + 2 * i) =
        __floats2half2_rn(eo.x * c - eo.y * s, eo.y * c + eo.x * s);
}

// ---------------------------------------------------------------------------
// fp16 causal flash attention, cp.async double-buffered.
// CTA: 128 q-rows x 1 head, 8 warps x 16 rows, 64-wide K tiles.
// Q pre-scaled (scale folded into w_q_up). KV tile = k_nope|v row-major
// (one contiguous 512B global segment), V fragments via ldmatrix.trans.
// ---------------------------------------------------------------------------
constexpr int QSH2  = 200;                      // Q row stride (halves)
constexpr int KVSH  = 264;                      // KV row stride (halves)
constexpr int KRSH  = 72;                       // krope row stride
constexpr int ATT_Q_BYTES  = 128 * QSH2 * 2;    // 51200
constexpr int ATT_KV_BYTES = 64 * KVSH * 2;     // 33792 per stage
constexpr int ATT_KR_BYTES = 64 * KRSH * 2;     // 9216 per stage
constexpr int ATT_SMEM_BYTES =
    ATT_Q_BYTES + 2 * ATT_KV_BYTES + 2 * ATT_KR_BYTES;  // 137216

__global__ void __launch_bounds__(256) attn_f16_kernel()
{
    extern __shared__ __half smh[];

    const int tid  = threadIdx.x;
    const int warp = tid >> 5;
    const int lane = tid & 31;
    const int g    = lane >> 2;
    const int tg   = lane & 3;
    const int bx   = blockIdx.x;
    const int qt   = (bx & 1) ? (15 - (bx >> 1)) : (bx >> 1);
    const int h    = blockIdx.y;
    const int qbase = qt * 128;
    const int r0   = warp * 16;

    const uint32_t s0   = (uint32_t)__cvta_generic_to_shared(smh);
    const uint32_t q_sm = s0;
    const uint32_t kv0  = s0 + ATT_Q_BYTES;
    const uint32_t kr0  = kv0 + 2 * ATT_KV_BYTES;

    // ---- async loaders -------------------------------------------------
    auto load_q = [&]() {
#pragma unroll
        for (int i = 0; i < 12; i++) {
            const int c   = tid + i * 256;       // 0..3071
            const int row = c / 24;
            const int seg = c % 24;
            const uint32_t d = q_sm + (row * QSH2 + seg * 8) * 2;
            const __half* gq = g_qh + (size_t)(qbase + row) * (NH * QKD)
                             + h * QKD + seg * 8;
            CP_ASYNC16(d, gq);
        }
    };
    auto load_kv = [&](int stage, int kbase) {
        const uint32_t kv = kv0 + stage * ATT_KV_BYTES;
        const uint32_t kr = kr0 + stage * ATT_KR_BYTES;
#pragma unroll
        for (int i = 0; i < 8; i++) {            // KV: 2048 chunks
            const int c   = tid + i * 256;
            const int row = c >> 5;
            const int seg = c & 31;
            const uint32_t d = kv + (row * KVSH + seg * 8) * 2;
            const __half* gk = g_kvuph + (size_t)(kbase + row) * (NH * KVUP_D)
                             + h * KVUP_D + seg * 8;
            CP_ASYNC16(d, gk);
        }
#pragma unroll
        for (int i = 0; i < 2; i++) {            // krope: 512 chunks
            const int c   = tid + i * 256;
            const int row = c >> 3;
            const int seg = c & 7;
            const uint32_t d = kr + (row * KRSH + seg * 8) * 2;
            const __half* gr = g_kropeh + (size_t)(kbase + row) * ROPE_D
                             + seg * 8;
            CP_ASYNC16(d, gr);
        }
    };

    // ldmatrix per-lane offsets
    const int aRow = lane & 15;
    const int aK8  = (lane >> 4) * 8;
    const uint32_t qa_off = q_sm + ((r0 + aRow) * QSH2 + aK8) * 2;
    const int bRowL = (lane & 7) + ((lane & 16) ? 8 : 0);
    const int bK8   = lane & 8;
    // V-trans: lane -> (k-row within 16, n-col block)
    const int vRow = lane & 15;
    const int vCol = (lane >> 4) * 8;

    float sacc[8][4];
    float oacc[16][4];
#pragma unroll
    for (int nv = 0; nv < 16; nv++)
#pragma unroll
        for (int v = 0; v < 4; v++) oacc[nv][v] = 0.f;
    float m0 = -INFINITY, m1 = -INFINITY, l0 = 0.f, l1 = 0.f;

    const int nkt = 2 * qt + 2;

    // prologue: Q + stage0 in one group
    load_q();
    load_kv(0, 0);
    asm volatile("cp.async.commit_group;");

    for (int kt = 0; kt < nkt; kt++) {
        const int kbase = kt * 64;

        if (kt + 1 < nkt) {
            load_kv((kt + 1) & 1, (kt + 1) * 64);
            asm volatile("cp.async.commit_group;");
            asm volatile("cp.async.wait_group 1;");
        } else {
            asm volatile("cp.async.wait_group 0;");
        }
        __syncthreads();

        const uint32_t kv = kv0 + (kt & 1) * ATT_KV_BYTES;
        const uint32_t kr = kr0 + (kt & 1) * ATT_KR_BYTES;

        // ---- S = Q K^T : 12 k16 steps (8 from KV, 4 from krope) --------
#pragma unroll
        for (int nf = 0; nf < 8; nf++)
#pragma unroll
            for (int v = 0; v < 4; v++) sacc[nf][v] = 0.f;

#pragma unroll
        for (int s16 = 0; s16 < 12; s16++) {
            uint32_t a0, a1, a2, a3;
            LDSM_X4(a0, a1, a2, a3, qa_off + s16 * 32);
#pragma unroll
            for (int nfp = 0; nfp < 4; nfp++) {
                uint32_t b0, b1, b2, b3;
                if (s16 < 8) {
                    LDSM_X4(b0, b1, b2, b3,
                            kv + ((nfp * 16 + bRowL) * KVSH + bK8) * 2
                               + s16 * 32);
                } else {
                    LDSM_X4(b0, b1, b2, b3,
                            kr + ((nfp * 16 + bRowL) * KRSH + bK8) * 2
                               + (s16 - 8) * 32);
                }
                MMA_F16(sacc[2*nfp][0], sacc[2*nfp][1],
                        sacc[2*nfp][2], sacc[2*nfp][3],
                        a0, a1, a2, a3, b0, b1);
                MMA_F16(sacc[2*nfp+1][0], sacc[2*nfp+1][1],
                        sacc[2*nfp+1][2], sacc[2*nfp+1][3],
                        a0, a1, a2, a3, b2, b3);
            }
        }

        // ---- causal mask ------------------------------------------------
        const int rg = qbase + r0 + g;
        if (kbase + 63 > rg) {
#pragma unroll
            for (int nf = 0; nf < 8; nf++) {
                const int c0 = kbase + nf * 8 + tg * 2;
                if (c0     > rg)     sacc[nf][0] = -INFINITY;
                if (c0 + 1 > rg)     sacc[nf][1] = -INFINITY;
                if (c0     > rg + 8) sacc[nf][2] = -INFINITY;
                if (c0 + 1 > rg + 8) sacc[nf][3] = -INFINITY;
            }
        }

        // ---- online softmax (fp32) --------------------------------------
        float t0 = -INFINITY, t1 = -INFINITY;
#pragma unroll
        for (int nf = 0; nf < 8; nf++) {
            t0 = fmaxf(t0, fmaxf(sacc[nf][0], sacc[nf][1]));
            t1 = fmaxf(t1, fmaxf(sacc[nf][2], sacc[nf][3]));
        }
        t0 = fmaxf(t0, __shfl_xor_sync(0xffffffffu, t0, 1));
        t0 = fmaxf(t0, __shfl_xor_sync(0xffffffffu, t0, 2));
        t1 = fmaxf(t1, __shfl_xor_sync(0xffffffffu, t1, 1));
        t1 = fmaxf(t1, __shfl_xor_sync(0xffffffffu, t1, 2));
        const float nm0 = fmaxf(m0, t0), nm1 = fmaxf(m1, t1);
        const float al0 = __expf(m0 - nm0), al1 = __expf(m1 - nm1);
        m0 = nm0; m1 = nm1;

        float rs0 = 0.f, rs1 = 0.f;
#pragma unroll
        for (int nf = 0; nf < 8; nf++) {
            sacc[nf][0] = __expf(sacc[nf][0] - nm0);
            sacc[nf][1] = __expf(sacc[nf][1] - nm0);
            sacc[nf][2] = __expf(sacc[nf][2] - nm1);
            sacc[nf][3] = __expf(sacc[nf][3] - nm1);
            rs0 += sacc[nf][0] + sacc[nf][1];
            rs1 += sacc[nf][2] + sacc[nf][3];
        }
        rs0 += __shfl_xor_sync(0xffffffffu, rs0, 1);
        rs0 += __shfl_xor_sync(0xffffffffu, rs0, 2);
        rs1 += __shfl_xor_sync(0xffffffffu, rs1, 1);
        rs1 += __shfl_xor_sync(0xffffffffu, rs1, 2);
        l0 = l0 * al0 + rs0;
        l1 = l1 * al1 + rs1;

#pragma unroll
        for (int nv = 0; nv < 16; nv++) {
            oacc[nv][0] *= al0; oacc[nv][1] *= al0;
            oacc[nv][2] *= al1; oacc[nv][3] *= al1;
        }

        // ---- O += P @ V (V via ldmatrix.trans from row-major KV tile) ---
#pragma unroll
        for (int s = 0; s < 4; s++) {
            const uint32_t pa0 = packh2(sacc[2*s][0],   sacc[2*s][1]);
            const uint32_t pa1 = packh2(sacc[2*s][2],   sacc[2*s][3]);
            const uint32_t pa2 = packh2(sacc[2*s+1][0], sacc[2*s+1][1]);
            const uint32_t pa3 = packh2(sacc[2*s+1][2], sacc[2*s+1][3]);
#pragma unroll
            for (int nvp = 0; nvp < 8; nvp++) {
                uint32_t b0, b1, b2, b3;
                LDSM_X4_T(b0, b1, b2, b3,
                          kv + ((s * 16 + vRow) * KVSH
                               + NOPE + nvp * 16 + vCol) * 2);
                MMA_F16(oacc[2*nvp][0], oacc[2*nvp][1],
                        oacc[2*nvp][2], oacc[2*nvp][3],
                        pa0, pa1, pa2, pa3, b0, b1);
                MMA_F16(oacc[2*nvp+1][0], oacc[2*nvp+1][1],
                        oacc[2*nvp+1][2], oacc[2*nvp+1][3],
                        pa0, pa1, pa2, pa3, b2, b3);
            }
        }
        __syncthreads();   // stage consumed; safe to overwrite next iter
    }

    // ---- epilogue --------------------------------------------------------
    const float inv0 = 1.f / l0, inv1 = 1.f / l1;
    const int rga = qbase + r0 + g;
#pragma unroll
    for (int nv = 0; nv < 16; nv++) {
        const int col = h * VDIM + nv * 8 + tg * 2;
        *reinterpret_cast<__half2*>(&g_attnh[(size_t)rga * (NH * VDIM) + col]) =
            __floats2half2_rn(oacc[nv][0] * inv0, oacc[nv][1] * inv0);
        *reinterpret_cast<__half2*>(&g_attnh[(size_t)(rga + 8) * (NH * VDIM) + col]) =
            __floats2half2_rn(oacc[nv][2] * inv1, oacc[nv][3] * inv1);
    }
}

// ---------------------------------------------------------------------------
// Launch helpers
// ---------------------------------------------------------------------------
static inline void launch_gemm_h(const __half* A, const __half* B, __half* C,
                                 int M, int N, int K)
{
    dim3 grid((N + GBN - 1) / GBN, M / GBM);
    gemm_f16_kernel<false, true><<<grid, 256, GEMM_SMEM>>>(
        A, B, C, nullptr, M, N, N, 0, K);
}
static inline void launch_gemm_f(const __half* A, const __half* B, float* C,
                                 int M, int N, int K)
{
    dim3 grid((N + GBN - 1) / GBN, M / GBM);
    gemm_f16_kernel<false, false><<<grid, 256, GEMM_SMEM>>>(
        A, B, C, nullptr, M, N, N, 0, K);
}
static inline void launch_gemm_split_h(const __half* A, const __half* B,
                                       __half* C1, __half* C2,
                                       int M, int N1, int N2, int K)
{
    const int N = N1 + N2;
    dim3 grid((N + GBN - 1) / GBN, M / GBM);
    gemm_f16_kernel<true, true><<<grid, 256, GEMM_SMEM>>>(
        A, B, C1, C2, M, N, N1, N2, K);
}
static inline void launch_f2h(const float* src, __half* dst, int n,
                              float scale = 1.f)
{
    const int n4 = n / 4;
    int grid = (n4 + 1023) / 1024;
    if (grid > 592) grid = 592;
    f2h_kernel<<<grid, 256>>>((const float4*)src, (h4*)dst, n4, scale);
}

extern "C" void kernel_launch(void* const* d_in, const int* in_sizes, int n_in,
                              void* d_out, int out_size)
{
    const float* x         = (const float*)d_in[0];
    const float* w_q_down  = (const float*)d_in[1];
    const float* q_norm_w  = (const float*)d_in[2];
    const float* w_q_up    = (const float*)d_in[3];
    const float* w_kv_down = (const float*)d_in[4];
    const float* kv_norm_w = (const float*)d_in[5];
    const float* w_kv_up   = (const float*)d_in[6];
    const float* w_o       = (const float*)d_in[7];
    float* out = (float*)d_out;

    __half *cqh, *kvh, *ckvh, *qh, *kvuph, *attnh;
    __half *xh, *wqkvdh, *wquh, *wkvuh, *woh;
    cudaGetSymbolAddress((void**)&cqh,    g_cqh);
    cudaGetSymbolAddress((void**)&kvh,    g_kvh);
    cudaGetSymbolAddress((void**)&ckvh,   g_ckvh);
    cudaGetSymbolAddress((void**)&qh,     g_qh);
    cudaGetSymbolAddress((void**)&kvuph,  g_kvuph);
    cudaGetSymbolAddress((void**)&attnh,  g_attnh);
    cudaGetSymbolAddress((void**)&xh,     g_xh);
    cudaGetSymbolAddress((void**)&wqkvdh, g_wqkvdh);
    cudaGetSymbolAddress((void**)&wquh,   g_wquh);
    cudaGetSymbolAddress((void**)&wkvuh,  g_wkvuh);
    cudaGetSymbolAddress((void**)&woh,    g_woh);

    cudaFuncSetAttribute(attn_f16_kernel,
                         cudaFuncAttributeMaxDynamicSharedMemorySize,
                         ATT_SMEM_BYTES);
    cudaFuncSetAttribute(gemm_f16_kernel<false, true>,
                         cudaFuncAttributeMaxDynamicSharedMemorySize, GEMM_SMEM);
    cudaFuncSetAttribute(gemm_f16_kernel<false, false>,
                         cudaFuncAttributeMaxDynamicSharedMemorySize, GEMM_SMEM);
    cudaFuncSetAttribute(gemm_f16_kernel<true, true>,
                         cudaFuncAttributeMaxDynamicSharedMemorySize, GEMM_SMEM);

    const float qscale = 0.07216878364870322f;  // 1/sqrt(192)

    // 0. half conversion (w_q_up pre-scaled by 1/sqrt(192))
    launch_f2h(x,         xh,                SEQ * DIM);
    launch_f2h(w_q_down,  wqkvdh,            QR * DIM);
    launch_f2h(w_kv_down, wqkvdh + QR * DIM, (KVR + ROPE_D) * DIM);
    launch_f2h(w_q_up,    wquh,              NH * QKD * QR, qscale);
    launch_f2h(w_kv_up,   wkvuh,             NH * KVUP_D * KVR);
    launch_f2h(w_o,       woh,               DIM * NH * VDIM);

    // 1. [c_q_pre | kv] = x @ [w_q_down; w_kv_down].T  (half outputs)
    launch_gemm_split_h(xh, wqkvdh, cqh, kvh, SEQ, QR, KVR + ROPE_D, DIM);
    // 2. c_q = rmsnorm(c_q_pre) (in place, half)
    rmsnorm_kernel<<<SEQ, 256>>>(cqh, cqh, q_norm_w, QR, QR, QR);
    // 3. q = c_q @ (w_q_up * 1/sqrt(192)).T -> half   [2048, 3072]
    launch_gemm_h(cqh, wquh, qh, SEQ, NH * QKD, QR);
    // 4. c_kv = rmsnorm(kv[:, :512]) -> half
    rmsnorm_kernel<<<SEQ, 256>>>(kvh, ckvh, kv_norm_w, KVR, KVR + ROPE_D, KVR);
    // 5. RoPE
    rope_tables_kernel<<<(SEQ * 32 + 255) / 256, 256>>>();
    rope_q_kernel<<<(SEQ * NH * 32 + 255) / 256, 256>>>();
    rope_k_kernel<<<(SEQ * 32 + 255) / 256, 256>>>();
    // 6. kv_up = c_kv @ w_kv_up.T -> half             [2048, 4096]
    launch_gemm_h(ckvh, wkvuh, kvuph, SEQ, NH * KVUP_D, KVR);
    // 7. pipelined fp16 causal attention -> g_attnh
    attn_f16_kernel<<<dim3(SEQ / 128, NH), 256, ATT_SMEM_BYTES>>>();
    // 8. out = attn @ w_o.T (fp32 out)                [2048, 2048]
    launch_gemm_f(attnh, woh, out, SEQ, DIM, NH * VDIM);
}

// round 13
// speedup vs baseline: 3.4722x; 1.0178x over previous
#include <cuda_runtime.h>
#include <cuda_fp16.h>
#include <math.h>
#include <stdint.h>

// ---------------------------------------------------------------------------
// Problem constants
// ---------------------------------------------------------------------------
constexpr int SEQ    = 2048;
constexpr int DIM    = 2048;
constexpr int NH     = 16;
constexpr int QR     = 1536;
constexpr int KVR    = 512;
constexpr int ROPE_D = 64;
constexpr int NOPE   = 128;
constexpr int VDIM   = 128;
constexpr int QKD    = NOPE + ROPE_D;          // 192
constexpr int KVUP_D = NOPE + VDIM;            // 256
constexpr float EPSF = 1e-6f;

// ---------------------------------------------------------------------------
// Scratch (device globals: allocation-free) — all-half intermediates
// ---------------------------------------------------------------------------
__device__ __align__(256) __half g_cqh  [SEQ * QR];
__device__ __align__(256) __half g_kvh  [SEQ * (KVR + ROPE_D)];
__device__ __align__(256) __half g_ckvh [SEQ * KVR];
__device__ __align__(256) __half g_qh   [SEQ * NH * QKD];      // scaled + roped
__device__ __align__(256) __half g_kropeh[SEQ * ROPE_D];
__device__ __align__(256) __half g_kvuph[SEQ * NH * KVUP_D];   // k_nope | v
__device__ __align__(256) __half g_attnh[SEQ * NH * VDIM];
__device__ __align__(256) float  g_cos  [SEQ * (ROPE_D / 2)];
__device__ __align__(256) float  g_sin  [SEQ * (ROPE_D / 2)];
// half operand copies
__device__ __align__(256) __half g_xh   [SEQ * DIM];
__device__ __align__(256) __half g_wqkvdh[(QR + KVR + ROPE_D) * DIM];
__device__ __align__(256) __half g_wquh [NH * QKD * QR];       // pre-scaled
__device__ __align__(256) __half g_wkvuh[NH * KVUP_D * KVR];
__device__ __align__(256) __half g_woh  [DIM * NH * VDIM];

// ---------------------------------------------------------------------------
// helpers
// ---------------------------------------------------------------------------
__device__ __forceinline__ uint32_t packh2(float a, float b) {
    __half2 h = __floats2half2_rn(a, b);
    return *reinterpret_cast<uint32_t*>(&h);
}

#define MMA_F16(D0,D1,D2,D3,A0,A1,A2,A3,B0,B1)                               \
    asm volatile(                                                            \
        "mma.sync.aligned.m16n8k16.row.col.f32.f16.f16.f32 "                 \
        "{%0,%1,%2,%3},{%4,%5,%6,%7},{%8,%9},{%0,%1,%2,%3};"                 \
        : "+f"(D0), "+f"(D1), "+f"(D2), "+f"(D3)                             \
        : "r"(A0), "r"(A1), "r"(A2), "r"(A3), "r"(B0), "r"(B1))

#define LDSM_X4(R0,R1,R2,R3,ADDR)                                            \
    asm volatile(                                                            \
        "ldmatrix.sync.aligned.m8n8.x4.shared.b16 {%0,%1,%2,%3}, [%4];"      \
        : "=r"(R0), "=r"(R1), "=r"(R2), "=r"(R3) : "r"(ADDR))

#define LDSM_X4_T(R0,R1,R2,R3,ADDR)                                          \
    asm volatile(                                                            \
        "ldmatrix.sync.aligned.m8n8.x4.trans.shared.b16 {%0,%1,%2,%3}, [%4];"\
        : "=r"(R0), "=r"(R1), "=r"(R2), "=r"(R3) : "r"(ADDR))

#define CP_ASYNC16(DST,SRC)                                                  \
    asm volatile("cp.async.cg.shared.global [%0], [%1], 16;"                 \
                 :: "r"(DST), "l"(SRC))

// 16-byte half vector (8 halves)
struct __align__(16) h8 { __half2 h[4]; };

// ---------------------------------------------------------------------------
// float -> half conversion (reads 2 float4 = 8 floats, writes one h8)
// ---------------------------------------------------------------------------
__global__ void __launch_bounds__(256) f2h_kernel(
    const float4* __restrict__ src, h8* __restrict__ dst, int n8, float scale)
{
    for (int i = blockIdx.x * 256 + threadIdx.x; i < n8; i += gridDim.x * 256) {
        const float4 v0 = src[2 * i];
        const float4 v1 = src[2 * i + 1];
        h8 o;
        o.h[0] = __floats2half2_rn(v0.x * scale, v0.y * scale);
        o.h[1] = __floats2half2_rn(v0.z * scale, v0.w * scale);
        o.h[2] = __floats2half2_rn(v1.x * scale, v1.y * scale);
        o.h[3] = __floats2half2_rn(v1.z * scale, v1.w * scale);
        dst[i] = o;
    }
}

// ---------------------------------------------------------------------------
// fp16 NT GEMM: C[M,N] = A[M,K](f16) * B[N,K](f16)^T
// 128x128 CTA, 8 warps x (64x32), m16n8k16, ldmatrix, 3-stage cp.async.
// HALF_OUT: write __half. SPLIT: cols [0,N1)->C, [N1,N)->C2.
// ROPEQ: fused RoPE on columns with (col % 192) >= 128 (rows = tokens).
// ---------------------------------------------------------------------------
constexpr int GBM = 128, GBN = 128, GBKH = 64, HSTR = 72;
constexpr int GTILE_H = (GBM + GBN) * HSTR;
constexpr int GSTAGES = 3;
constexpr int GEMM_SMEM = GSTAGES * GTILE_H * 2;
constexpr int A_OFF_B  = GBM * HSTR * 2;

template<bool SPLIT, bool HALF_OUT, bool ROPEQ>
__global__ void __launch_bounds__(256, 2) gemm_f16_kernel(
    const __half* __restrict__ A, const __half* __restrict__ B,
    void* __restrict__ C, void* __restrict__ C2,
    int M, int N, int N1, int N2, int K)
{
    extern __shared__ __half smh[];

    const int tid  = threadIdx.x;
    const int warp = tid >> 5;
    const int lane = tid & 31;
    const int g    = lane >> 2;
    const int tg   = lane & 3;
    const int wm   = (warp & 1) * 64;
    const int wn   = (warp >> 1) * 32;
    const int bm0  = blockIdx.y * GBM;
    const int bn0  = blockIdx.x * GBN;

    const uint32_t s0 = (uint32_t)__cvta_generic_to_shared(smh);

    auto load_tiles = [&](int slot, int k0) {
        const uint32_t sA = s0 + slot * (GTILE_H * 2);
        const uint32_t sB = sA + A_OFF_B;
#pragma unroll
        for (int i = 0; i < 4; i++) {
            const int c   = tid + i * 256;
            const int row = c >> 3;
            const int seg = c & 7;
            const uint32_t da = sA + (row * HSTR + seg * 8) * 2;
            const __half* ga = A + (size_t)(bm0 + row) * K + k0 + seg * 8;
            CP_ASYNC16(da, ga);
        }
#pragma unroll
        for (int i = 0; i < 4; i++) {
            const int c   = tid + i * 256;
            const int row = c >> 3;
            const int seg = c & 7;
            const int rb  = bn0 + row;
            const int ok  = (rb < N) ? 16 : 0;
            const __half* gb = B + (size_t)(ok ? rb : 0) * K + k0 + seg * 8;
            const uint32_t db = sB + (row * HSTR + seg * 8) * 2;
            asm volatile("cp.async.cg.shared.global [%0], [%1], 16, %2;"
                         :: "r"(db), "l"(gb), "r"(ok));
        }
    };

    float acc[4][4][4];
#pragma unroll
    for (int mt = 0; mt < 4; mt++)
#pragma unroll
        for (int nt = 0; nt < 4; nt++)
#pragma unroll
            for (int v = 0; v < 4; v++) acc[mt][nt][v] = 0.f;

    const int nk = K / GBKH;

#pragma unroll
    for (int s = 0; s < GSTAGES - 1; s++) {
        if (s < nk) load_tiles(s, s * GBKH);
        asm volatile("cp.async.commit_group;");
    }

    const int aRow = lane & 15;
    const int aK8  = (lane >> 4) * 8;
    uint32_t aOff[4];
#pragma unroll
    for (int mt = 0; mt < 4; mt++)
        aOff[mt] = ((wm + mt * 16 + aRow) * HSTR + aK8) * 2;
    const int bRowL = (lane & 7) + ((lane & 16) ? 8 : 0);
    const int bK8   = lane & 8;
    uint32_t bOff[2];
#pragma unroll
    for (int p = 0; p < 2; p++)
        bOff[p] = ((wn + p * 16 + bRowL) * HSTR + bK8) * 2 + A_OFF_B;

    for (int kt = 0; kt < nk; kt++) {
        asm volatile("cp.async.wait_group %0;" :: "n"(GSTAGES - 2));
        __syncthreads();

        if (kt + GSTAGES - 1 < nk)
            load_tiles((kt + GSTAGES - 1) % GSTAGES, (kt + GSTAGES - 1) * GBKH);
        asm volatile("cp.async.commit_group;");

        const uint32_t sbase = s0 + (kt % GSTAGES) * (GTILE_H * 2);

#pragma unroll
        for (int s16 = 0; s16 < GBKH / 16; s16++) {
            const uint32_t kb = sbase + s16 * 32;
            uint32_t af[4][4], bf[4][2];
#pragma unroll
            for (int mt = 0; mt < 4; mt++)
                LDSM_X4(af[mt][0], af[mt][1], af[mt][2], af[mt][3],
                        kb + aOff[mt]);
#pragma unroll
            for (int p = 0; p < 2; p++)
                LDSM_X4(bf[2*p][0], bf[2*p][1], bf[2*p+1][0], bf[2*p+1][1],
                        kb + bOff[p]);
#pragma unroll
            for (int mt = 0; mt < 4; mt++)
#pragma unroll
                for (int nt = 0; nt < 4; nt++)
                    MMA_F16(acc[mt][nt][0], acc[mt][nt][1],
                            acc[mt][nt][2], acc[mt][nt][3],
                            af[mt][0], af[mt][1], af[mt][2], af[mt][3],
                            bf[nt][0], bf[nt][1]);
        }
    }

    void* Cbv; int Nw, c0;
    if (SPLIT && bn0 >= N1) { Cbv = C2; Nw = N2; c0 = bn0 - N1; }
    else                    { Cbv = C;  Nw = SPLIT ? N1 : N; c0 = bn0; }

#pragma unroll
    for (int mt = 0; mt < 4; mt++) {
        const int r0 = bm0 + wm + mt * 16 + g;
#pragma unroll
        for (int nt = 0; nt < 4; nt++) {
            const int cc = c0 + wn + nt * 8 + tg * 2;
            if (cc < Nw) {
                if (ROPEQ) {
                    const int d = cc % QKD;
                    if (d >= NOPE) {
                        const int ip = (d - NOPE) >> 1;
                        {
                            const float cv = g_cos[(size_t)r0 * 32 + ip];
                            const float sv = g_sin[(size_t)r0 * 32 + ip];
                            const float e = acc[mt][nt][0], o = acc[mt][nt][1];
                            acc[mt][nt][0] = e * cv - o * sv;
                            acc[mt][nt][1] = o * cv + e * sv;
                        }
                        {
                            const float cv = g_cos[(size_t)(r0 + 8) * 32 + ip];
                            const float sv = g_sin[(size_t)(r0 + 8) * 32 + ip];
                            const float e = acc[mt][nt][2], o = acc[mt][nt][3];
                            acc[mt][nt][2] = e * cv - o * sv;
                            acc[mt][nt][3] = o * cv + e * sv;
                        }
                    }
                }
                if (HALF_OUT) {
                    __half* Ch = (__half*)Cbv;
                    *reinterpret_cast<__half2*>(&Ch[(size_t)r0 * Nw + cc]) =
                        __floats2half2_rn(acc[mt][nt][0], acc[mt][nt][1]);
                    *reinterpret_cast<__half2*>(&Ch[(size_t)(r0 + 8) * Nw + cc]) =
                        __floats2half2_rn(acc[mt][nt][2], acc[mt][nt][3]);
                } else {
                    float* Cf = (float*)Cbv;
                    *reinterpret_cast<float2*>(&Cf[(size_t)r0 * Nw + cc]) =
                        make_float2(acc[mt][nt][0], acc[mt][nt][1]);
                    *reinterpret_cast<float2*>(&Cf[(size_t)(r0 + 8) * Nw + cc]) =
                        make_float2(acc[mt][nt][2], acc[mt][nt][3]);
                }
            }
        }
    }
}

// ---------------------------------------------------------------------------
// RMSNorm — half in/out, 8-half (16B) vectorized, reduction in fp32.
// Requires R % 8 == 0, strides % 8 == 0 (hold: 1536/1536, 576/512).
// ---------------------------------------------------------------------------
__global__ void __launch_bounds__(256) rmsnorm_kernel(
    const __half* __restrict__ src, __half* __restrict__ dst,
    const float* __restrict__ w, int R, int sstride, int dstride)
{
    const int row = blockIdx.x;
    const h8* s8 = reinterpret_cast<const h8*>(src + (size_t)row * sstride);
    h8* d8 = reinterpret_cast<h8*>(dst + (size_t)row * dstride);
    const float4* w4 = reinterpret_cast<const float4*>(w);
    const int n8 = R >> 3;

    float sum = 0.f;
    for (int i = threadIdx.x; i < n8; i += 256) {
        const h8 v = s8[i];
#pragma unroll
        for (int j = 0; j < 4; j++) {
            const float2 p = __half22float2(v.h[j]);
            sum = fmaf(p.x, p.x, sum);
            sum = fmaf(p.y, p.y, sum);
        }
    }
    __shared__ float red[8];
#pragma unroll
    for (int o = 16; o; o >>= 1) sum += __shfl_down_sync(0xffffffffu, sum, o);
    if ((threadIdx.x & 31) == 0) red[threadIdx.x >> 5] = sum;
    __syncthreads();
    if (threadIdx.x < 8) {
        float v = red[threadIdx.x];
#pragma unroll
        for (int o = 4; o; o >>= 1) v += __shfl_down_sync(0xffu, v, o);
        if (threadIdx.x == 0) red[0] = v;
    }
    __syncthreads();
    const float mean = red[0] / (float)R;
    const float r = rsqrtf(mean + EPSF);

    for (int i = threadIdx.x; i < n8; i += 256) {
        const h8 v = s8[i];
        const float4 w0 = w4[2 * i];
        const float4 w1 = w4[2 * i + 1];
        const float2 a = __half22float2(v.h[0]);
        const float2 b = __half22float2(v.h[1]);
        const float2 c = __half22float2(v.h[2]);
        const float2 d = __half22float2(v.h[3]);
        h8 o;
        o.h[0] = __floats2half2_rn(a.x * r * w0.x, a.y * r * w0.y);
        o.h[1] = __floats2half2_rn(b.x * r * w0.z, b.y * r * w0.w);
        o.h[2] = __floats2half2_rn(c.x * r * w1.x, c.y * r * w1.y);
        o.h[3] = __floats2half2_rn(d.x * r * w1.z, d.y * r * w1.w);
        d8[i] = o;
    }
}

// ---------------------------------------------------------------------------
// RoPE tables + k_rope
// ---------------------------------------------------------------------------
__global__ void rope_tables_kernel()
{
    const int idx = blockIdx.x * blockDim.x + threadIdx.x;
    if (idx >= SEQ * (ROPE_D / 2)) return;
    const int t = idx / (ROPE_D / 2);
    const int i = idx % (ROPE_D / 2);
    const double freq = pow(500000.0, -(double)i / 32.0);
    const float ang = (float)t * (float)freq;
    g_cos[idx] = cosf(ang);
    g_sin[idx] = sinf(ang);
}

__global__ void rope_k_kernel()
{
    const int idx = blockIdx.x * blockDim.x + threadIdx.x;
    if (idx >= SEQ * (ROPE_D / 2)) return;
    const int i = idx & 31;
    const int t = idx >> 5;
    const float c = g_cos[t * 32 + i];
    const float s = g_sin[t * 32 + i];
    const __half2 src = *reinterpret_cast<const __half2*>(
        g_kvh + (size_t)t * (KVR + ROPE_D) + KVR + 2 * i);
    const float2 eo = __half22float2(src);
    *reinterpret_cast<__half2*>(g_kropeh + t * ROPE_D + 2 * i) =
        __floats2half2_rn(eo.x * c - eo.y * s, eo.y * c + eo.x * s);
}

// ---------------------------------------------------------------------------
// fp16 causal flash attention (unchanged from R11)
// ---------------------------------------------------------------------------
constexpr int QSH2  = 200;
constexpr int KVSH  = 264;
constexpr int KRSH  = 72;
constexpr int ATT_Q_BYTES  = 128 * QSH2 * 2;
constexpr int ATT_KV_BYTES = 64 * KVSH * 2;
constexpr int ATT_KR_BYTES = 64 * KRSH * 2;
constexpr int ATT_SMEM_BYTES =
    ATT_Q_BYTES + 2 * ATT_KV_BYTES + 2 * ATT_KR_BYTES;

__global__ void __launch_bounds__(256) attn_f16_kernel()
{
    extern __shared__ __half smh[];

    const int tid  = threadIdx.x;
    const int warp = tid >> 5;
    const int lane = tid & 31;
    const int g    = lane >> 2;
    const int tg   = lane & 3;
    const int bx   = blockIdx.x;
    const int qt   = (bx & 1) ? (15 - (bx >> 1)) : (bx >> 1);
    const int h    = blockIdx.y;
    const int qbase = qt * 128;
    const int r0   = warp * 16;

    const uint32_t s0   = (uint32_t)__cvta_generic_to_shared(smh);
    const uint32_t q_sm = s0;
    const uint32_t kv0  = s0 + ATT_Q_BYTES;
    const uint32_t kr0  = kv0 + 2 * ATT_KV_BYTES;

    auto load_q = [&]() {
#pragma unroll
        for (int i = 0; i < 12; i++) {
            const int c   = tid + i * 256;
            const int row = c / 24;
            const int seg = c % 24;
            const uint32_t d = q_sm + (row * QSH2 + seg * 8) * 2;
            const __half* gq = g_qh + (size_t)(qbase + row) * (NH * QKD)
                             + h * QKD + seg * 8;
            CP_ASYNC16(d, gq);
        }
    };
    auto load_kv = [&](int stage, int kbase) {
        const uint32_t kv = kv0 + stage * ATT_KV_BYTES;
        const uint32_t kr = kr0 + stage * ATT_KR_BYTES;
#pragma unroll
        for (int i = 0; i < 8; i++) {
            const int c   = tid + i * 256;
            const int row = c >> 5;
            const int seg = c & 31;
            const uint32_t d = kv + (row * KVSH + seg * 8) * 2;
            const __half* gk = g_kvuph + (size_t)(kbase + row) * (NH * KVUP_D)
                             + h * KVUP_D + seg * 8;
            CP_ASYNC16(d, gk);
        }
#pragma unroll
        for (int i = 0; i < 2; i++) {
            const int c   = tid + i * 256;
            const int row = c >> 3;
            const int seg = c & 7;
            const uint32_t d = kr + (row * KRSH + seg * 8) * 2;
            const __half* gr = g_kropeh + (size_t)(kbase + row) * ROPE_D
                             + seg * 8;
            CP_ASYNC16(d, gr);
        }
    };

    const int aRow = lane & 15;
    const int aK8  = (lane >> 4) * 8;
    const uint32_t qa_off = q_sm + ((r0 + aRow) * QSH2 + aK8) * 2;
    const int bRowL = (lane & 7) + ((lane & 16) ? 8 : 0);
    const int bK8   = lane & 8;
    const int vRow = lane & 15;
    const int vCol = (lane >> 4) * 8;

    float sacc[8][4];
    float oacc[16][4];
#pragma unroll
    for (int nv = 0; nv < 16; nv++)
#pragma unroll
        for (int v = 0; v < 4; v++) oacc[nv][v] = 0.f;
    float m0 = -INFINITY, m1 = -INFINITY, l0 = 0.f, l1 = 0.f;

    const int nkt = 2 * qt + 2;

    load_q();
    load_kv(0, 0);
    asm volatile("cp.async.commit_group;");

    for (int kt = 0; kt < nkt; kt++) {
        const int kbase = kt * 64;

        if (kt + 1 < nkt) {
            load_kv((kt + 1) & 1, (kt + 1) * 64);
            asm volatile("cp.async.commit_group;");
            asm volatile("cp.async.wait_group 1;");
        } else {
            asm volatile("cp.async.wait_group 0;");
        }
        __syncthreads();

        const uint32_t kv = kv0 + (kt & 1) * ATT_KV_BYTES;
        const uint32_t kr = kr0 + (kt & 1) * ATT_KR_BYTES;

#pragma unroll
        for (int nf = 0; nf < 8; nf++)
#pragma unroll
            for (int v = 0; v < 4; v++) sacc[nf][v] = 0.f;

#pragma unroll
        for (int s16 = 0; s16 < 12; s16++) {
            uint32_t a0, a1, a2, a3;
            LDSM_X4(a0, a1, a2, a3, qa_off + s16 * 32);
#pragma unroll
            for (int nfp = 0; nfp < 4; nfp++) {
                uint32_t b0, b1, b2, b3;
                if (s16 < 8) {
                    LDSM_X4(b0, b1, b2, b3,
                            kv + ((nfp * 16 + bRowL) * KVSH + bK8) * 2
                               + s16 * 32);
                } else {
                    LDSM_X4(b0, b1, b2, b3,
                            kr + ((nfp * 16 + bRowL) * KRSH + bK8) * 2
                               + (s16 - 8) * 32);
                }
                MMA_F16(sacc[2*nfp][0], sacc[2*nfp][1],
                        sacc[2*nfp][2], sacc[2*nfp][3],
                        a0, a1, a2, a3, b0, b1);
                MMA_F16(sacc[2*nfp+1][0], sacc[2*nfp+1][1],
                        sacc[2*nfp+1][2], sacc[2*nfp+1][3],
                        a0, a1, a2, a3, b2, b3);
            }
        }

        const int rg = qbase + r0 + g;
        if (kbase + 63 > rg) {
#pragma unroll
            for (int nf = 0; nf < 8; nf++) {
                const int c0 = kbase + nf * 8 + tg * 2;
                if (c0     > rg)     sacc[nf][0] = -INFINITY;
                if (c0 + 1 > rg)     sacc[nf][1] = -INFINITY;
                if (c0     > rg + 8) sacc[nf][2] = -INFINITY;
                if (c0 + 1 > rg + 8) sacc[nf][3] = -INFINITY;
            }
        }

        float t0 = -INFINITY, t1 = -INFINITY;
#pragma unroll
        for (int nf = 0; nf < 8; nf++) {
            t0 = fmaxf(t0, fmaxf(sacc[nf][0], sacc[nf][1]));
            t1 = fmaxf(t1, fmaxf(sacc[nf][2], sacc[nf][3]));
        }
        t0 = fmaxf(t0, __shfl_xor_sync(0xffffffffu, t0, 1));
        t0 = fmaxf(t0, __shfl_xor_sync(0xffffffffu, t0, 2));
        t1 = fmaxf(t1, __shfl_xor_sync(0xffffffffu, t1, 1));
        t1 = fmaxf(t1, __shfl_xor_sync(0xffffffffu, t1, 2));
        const float nm0 = fmaxf(m0, t0), nm1 = fmaxf(m1, t1);
        const float al0 = __expf(m0 - nm0), al1 = __expf(m1 - nm1);
        m0 = nm0; m1 = nm1;

        float rs0 = 0.f, rs1 = 0.f;
#pragma unroll
        for (int nf = 0; nf < 8; nf++) {
            sacc[nf][0] = __expf(sacc[nf][0] - nm0);
            sacc[nf][1] = __expf(sacc[nf][1] - nm0);
            sacc[nf][2] = __expf(sacc[nf][2] - nm1);
            sacc[nf][3] = __expf(sacc[nf][3] - nm1);
            rs0 += sacc[nf][0] + sacc[nf][1];
            rs1 += sacc[nf][2] + sacc[nf][3];
        }
        rs0 += __shfl_xor_sync(0xffffffffu, rs0, 1);
        rs0 += __shfl_xor_sync(0xffffffffu, rs0, 2);
        rs1 += __shfl_xor_sync(0xffffffffu, rs1, 1);
        rs1 += __shfl_xor_sync(0xffffffffu, rs1, 2);
        l0 = l0 * al0 + rs0;
        l1 = l1 * al1 + rs1;

#pragma unroll
        for (int nv = 0; nv < 16; nv++) {
            oacc[nv][0] *= al0; oacc[nv][1] *= al0;
            oacc[nv][2] *= al1; oacc[nv][3] *= al1;
        }

#pragma unroll
        for (int s = 0; s < 4; s++) {
            const uint32_t pa0 = packh2(sacc[2*s][0],   sacc[2*s][1]);
            const uint32_t pa1 = packh2(sacc[2*s][2],   sacc[2*s][3]);
            const uint32_t pa2 = packh2(sacc[2*s+1][0], sacc[2*s+1][1]);
            const uint32_t pa3 = packh2(sacc[2*s+1][2], sacc[2*s+1][3]);
#pragma unroll
            for (int nvp = 0; nvp < 8; nvp++) {
                uint32_t b0, b1, b2, b3;
                LDSM_X4_T(b0, b1, b2, b3,
                          kv + ((s * 16 + vRow) * KVSH
                               + NOPE + nvp * 16 + vCol) * 2);
                MMA_F16(oacc[2*nvp][0], oacc[2*nvp][1],
                        oacc[2*nvp][2], oacc[2*nvp][3],
                        pa0, pa1, pa2, pa3, b0, b1);
                MMA_F16(oacc[2*nvp+1][0], oacc[2*nvp+1][1],
                        oacc[2*nvp+1][2], oacc[2*nvp+1][3],
                        pa0, pa1, pa2, pa3, b2, b3);
            }
        }
        __syncthreads();
    }

    const float inv0 = 1.f / l0, inv1 = 1.f / l1;
    const int rga = qbase + r0 + g;
#pragma unroll
    for (int nv = 0; nv < 16; nv++) {
        const int col = h * VDIM + nv * 8 + tg * 2;
        *reinterpret_cast<__half2*>(&g_attnh[(size_t)rga * (NH * VDIM) + col]) =
            __floats2half2_rn(oacc[nv][0] * inv0, oacc[nv][1] * inv0);
        *reinterpret_cast<__half2*>(&g_attnh[(size_t)(rga + 8) * (NH * VDIM) + col]) =
            __floats2half2_rn(oacc[nv][2] * inv1, oacc[nv][3] * inv1);
    }
}

// ---------------------------------------------------------------------------
// Launch helpers
// ---------------------------------------------------------------------------
static inline void launch_gemm_h(const __half* A, const __half* B, __half* C,
                                 int M, int N, int K)
{
    dim3 grid((N + GBN - 1) / GBN, M / GBM);
    gemm_f16_kernel<false, true, false><<<grid, 256, GEMM_SMEM>>>(
        A, B, C, nullptr, M, N, N, 0, K);
}
static inline void launch_gemm_h_rope(const __half* A, const __half* B,
                                      __half* C, int M, int N, int K)
{
    dim3 grid((N + GBN - 1) / GBN, M / GBM);
    gemm_f16_kernel<false, true, true><<<grid, 256, GEMM_SMEM>>>(
        A, B, C, nullptr, M, N, N, 0, K);
}
static inline void launch_gemm_f(const __half* A, const __half* B, float* C,
                                 int M, int N, int K)
{
    dim3 grid((N + GBN - 1) / GBN, M / GBM);
    gemm_f16_kernel<false, false, false><<<grid, 256, GEMM_SMEM>>>(
        A, B, C, nullptr, M, N, N, 0, K);
}
static inline void launch_gemm_split_h(const __half* A, const __half* B,
                                       __half* C1, __half* C2,
                                       int M, int N1, int N2, int K)
{
    const int N = N1 + N2;
    dim3 grid((N + GBN - 1) / GBN, M / GBM);
    gemm_f16_kernel<true, true, false><<<grid, 256, GEMM_SMEM>>>(
        A, B, C1, C2, M, N, N1, N2, K);
}
static inline void launch_f2h(const float* src, __half* dst, int n,
                              float scale = 1.f)
{
    const int n8 = n / 8;
    int grid = (n8 + 1023) / 1024;
    if (grid > 592) grid = 592;
    f2h_kernel<<<grid, 256>>>((const float4*)src, (h8*)dst, n8, scale);
}

extern "C" void kernel_launch(void* const* d_in, const int* in_sizes, int n_in,
                              void* d_out, int out_size)
{
    const float* x         = (const float*)d_in[0];
    const float* w_q_down  = (const float*)d_in[1];
    const float* q_norm_w  = (const float*)d_in[2];
    const float* w_q_up    = (const float*)d_in[3];
    const float* w_kv_down = (const float*)d_in[4];
    const float* kv_norm_w = (const float*)d_in[5];
    const float* w_kv_up   = (const float*)d_in[6];
    const float* w_o       = (const float*)d_in[7];
    float* out = (float*)d_out;

    __half *cqh, *kvh, *ckvh, *qh, *kvuph, *attnh;
    __half *xh, *wqkvdh, *wquh, *wkvuh, *woh;
    cudaGetSymbolAddress((void**)&cqh,    g_cqh);
    cudaGetSymbolAddress((void**)&kvh,    g_kvh);
    cudaGetSymbolAddress((void**)&ckvh,   g_ckvh);
    cudaGetSymbolAddress((void**)&qh,     g_qh);
    cudaGetSymbolAddress((void**)&kvuph,  g_kvuph);
    cudaGetSymbolAddress((void**)&attnh,  g_attnh);
    cudaGetSymbolAddress((void**)&xh,     g_xh);
    cudaGetSymbolAddress((void**)&wqkvdh, g_wqkvdh);
    cudaGetSymbolAddress((void**)&wquh,   g_wquh);
    cudaGetSymbolAddress((void**)&wkvuh,  g_wkvuh);
    cudaGetSymbolAddress((void**)&woh,    g_woh);

    cudaFuncSetAttribute(attn_f16_kernel,
                         cudaFuncAttributeMaxDynamicSharedMemorySize,
                         ATT_SMEM_BYTES);
    cudaFuncSetAttribute((void*)gemm_f16_kernel<false, true, false>,
                         cudaFuncAttributeMaxDynamicSharedMemorySize, GEMM_SMEM);
    cudaFuncSetAttribute((void*)gemm_f16_kernel<false, true, true>,
                         cudaFuncAttributeMaxDynamicSharedMemorySize, GEMM_SMEM);
    cudaFuncSetAttribute((void*)gemm_f16_kernel<false, false, false>,
                         cudaFuncAttributeMaxDynamicSharedMemorySize, GEMM_SMEM);
    cudaFuncSetAttribute((void*)gemm_f16_kernel<true, true, false>,
                         cudaFuncAttributeMaxDynamicSharedMemorySize, GEMM_SMEM);

    const float qscale = 0.07216878364870322f;  // 1/sqrt(192)

    // 0. rope tables (needed by q-GEMM epilogue) + half conversions
    rope_tables_kernel<<<(SEQ * 32 + 255) / 256, 256>>>();
    launch_f2h(x,         xh,                SEQ * DIM);
    launch_f2h(w_q_down,  wqkvdh,            QR * DIM);
    launch_f2h(w_kv_down, wqkvdh + QR * DIM, (KVR + ROPE_D) * DIM);
    launch_f2h(w_q_up,    wquh,              NH * QKD * QR, qscale);
    launch_f2h(w_kv_up,   wkvuh,             NH * KVUP_D * KVR);
    launch_f2h(w_o,       woh,               DIM * NH * VDIM);

    // 1. [c_q_pre | kv] = x @ [w_q_down; w_kv_down].T  (half outputs)
    launch_gemm_split_h(xh, wqkvdh, cqh, kvh, SEQ, QR, KVR + ROPE_D, DIM);
    // 2. c_q = rmsnorm(c_q_pre) (in place, vectorized)
    rmsnorm_kernel<<<SEQ, 256>>>(cqh, cqh, q_norm_w, QR, QR, QR);
    // 3. q = c_q @ (w_q_up * scale).T with fused RoPE -> half
    launch_gemm_h_rope(cqh, wquh, qh, SEQ, NH * QKD, QR);
    // 4. c_kv = rmsnorm(kv[:, :512]) -> half
    rmsnorm_kernel<<<SEQ, 256>>>(kvh, ckvh, kv_norm_w, KVR, KVR + ROPE_D, KVR);
    // 5. k_rope
    rope_k_kernel<<<(SEQ * 32 + 255) / 256, 256>>>();
    // 6. kv_up = c_kv @ w_kv_up.T -> half
    launch_gemm_h(ckvh, wkvuh, kvuph, SEQ, NH * KVUP_D, KVR);
    // 7. pipelined fp16 causal attention -> g_attnh
    attn_f16_kernel<<<dim3(SEQ / 128, NH), 256, ATT_SMEM_BYTES>>>();
    // 8. out = attn @ w_o.T (fp32 out)
    launch_gemm_f(attnh, woh, out, SEQ, DIM, NH * VDIM);
}